// round 1
// baseline (speedup 1.0000x reference)
#include <cuda_runtime.h>
#include <math.h>

#define NG 50000
#define NS 10000
#define EG 800000
#define ES 160000

// ---- scratch layout (single __device__ array, no allocations) ----
static const size_t OFF_AGG  = 0;               // up to 50000*256 = 12.8M floats
static const size_t OFF_X1   = 12800000;        // 50000*128 = 6.4M
static const size_t OFF_X2   = 19200000;        // 50000*256 = 12.8M
static const size_t OFF_X3   = 32000000;        // 50000*192 = 9.6M
static const size_t OFF_WT   = 41600000;        // max 512*192 = 98304
static const size_t OFF_POOL = 41700000;        // 2 * 8 * 192 = 3072
static const size_t OFF_CNT  = 41703072;        // 16
__device__ float d_scratch[41703168];

// ---------------- zero ----------------
__global__ void zero_k(float4* p, int n4) {
    int i = blockIdx.x * blockDim.x + threadIdx.x;
    if (i < n4) p[i] = make_float4(0.f, 0.f, 0.f, 0.f);
}

// ---------------- fuse + transpose weights: Wt[k][n], k in [0,2c) ----------------
__global__ void fuse_w(const float* __restrict__ Wr, const float* __restrict__ Wn,
                       float* __restrict__ Wt, int c, int o) {
    int idx = blockIdx.x * blockDim.x + threadIdx.x;
    int total = 2 * c * o;
    if (idx >= total) return;
    int k = idx / o, n = idx - k * o;
    Wt[idx] = (k < c) ? Wr[n * c + k] : Wn[n * c + (k - c)];
}

// ---------------- edge scatter-add: agg[dst] += x[src] ----------------
__global__ void scatter_add(const float* __restrict__ x, const int* __restrict__ ei,
                            int E, int c, float* __restrict__ agg) {
    int g = c >> 2;
    int idx = blockIdx.x * blockDim.x + threadIdx.x;
    if (idx >= E * g) return;
    int e = idx / g;
    int j = (idx - e * g) << 2;
    int src = ei[e];
    int dst = ei[E + e];
    float4 v = *(const float4*)(x + (size_t)src * c + j);
    float* p = agg + (size_t)dst * c + j;
    atomicAdd(p + 0, v.x);
    atomicAdd(p + 1, v.y);
    atomicAdd(p + 2, v.z);
    atomicAdd(p + 3, v.w);
}

// ---------------- fused GraphConv GEMM: out = ELU([A1|A2] @ Wt + bias) ----------------
// A1 = agg (N x c), A2 = x (N x c), Wt (2c x o, k-major), out (N x o).
// 64x64 tile, TK=32, 256 threads, 4x4 micro-tile.
__global__ void gemm_fused(const float* __restrict__ A1, const float* __restrict__ A2,
                           const float* __restrict__ Wt, const float* __restrict__ bias,
                           float* __restrict__ out, int Nrows, int c, int o) {
    __shared__ float As[64][33];   // [mm][kk], padded -> conflict-free
    __shared__ float Bs[32][64];   // [kk][nn]
    int tid = threadIdx.x;
    int tx = tid & 15, ty = tid >> 4;
    int m0 = blockIdx.y * 64, n0 = blockIdx.x * 64;
    float acc[4][4] = {};
    int K = 2 * c;
    int kkl = tid & 31, mmb = tid >> 5;   // A-tile loader coords
    int nnl = tid & 63, kbl = tid >> 6;   // B-tile loader coords

    for (int k0 = 0; k0 < K; k0 += 32) {
        const float* A = (k0 < c) ? A1 : A2;
        int col0 = (k0 < c) ? k0 : (k0 - c);
        #pragma unroll
        for (int p = 0; p < 8; p++) {
            int mm = p * 8 + mmb;
            int m = m0 + mm;
            As[mm][kkl] = (m < Nrows) ? A[(size_t)m * c + col0 + kkl] : 0.f;
        }
        #pragma unroll
        for (int p = 0; p < 8; p++) {
            int kk = p * 4 + kbl;
            Bs[kk][nnl] = Wt[(size_t)(k0 + kk) * o + n0 + nnl];
        }
        __syncthreads();
        #pragma unroll
        for (int kk = 0; kk < 32; kk++) {
            float4 b4 = *(const float4*)&Bs[kk][tx * 4];
            float a0 = As[ty * 4 + 0][kk];
            float a1 = As[ty * 4 + 1][kk];
            float a2 = As[ty * 4 + 2][kk];
            float a3 = As[ty * 4 + 3][kk];
            acc[0][0] += a0 * b4.x; acc[0][1] += a0 * b4.y; acc[0][2] += a0 * b4.z; acc[0][3] += a0 * b4.w;
            acc[1][0] += a1 * b4.x; acc[1][1] += a1 * b4.y; acc[1][2] += a1 * b4.z; acc[1][3] += a1 * b4.w;
            acc[2][0] += a2 * b4.x; acc[2][1] += a2 * b4.y; acc[2][2] += a2 * b4.z; acc[2][3] += a2 * b4.w;
            acc[3][0] += a3 * b4.x; acc[3][1] += a3 * b4.y; acc[3][2] += a3 * b4.z; acc[3][3] += a3 * b4.w;
        }
        __syncthreads();
    }

    #pragma unroll
    for (int i = 0; i < 4; i++) {
        int m = m0 + ty * 4 + i;
        if (m >= Nrows) continue;
        #pragma unroll
        for (int j = 0; j < 4; j++) {
            int n = n0 + tx * 4 + j;
            float v = acc[i][j] + bias[n];
            out[(size_t)m * o + n] = (v > 0.f) ? v : expm1f(v);
        }
    }
}

// ---------------- batch pooling ----------------
__global__ void pool_count(const int* __restrict__ batch, int N, float* __restrict__ cnt) {
    int i = blockIdx.x * blockDim.x + threadIdx.x;
    if (i < N) atomicAdd(&cnt[batch[i]], 1.0f);
}

__global__ void pool_sum(const float* __restrict__ x, const int* __restrict__ batch,
                         int N, float* __restrict__ pool) {
    int idx = blockIdx.x * blockDim.x + threadIdx.x;
    if (idx >= N * 48) return;
    int i = idx / 48;
    int j = (idx - i * 48) << 2;
    int b = batch[i];
    float4 v = *(const float4*)(x + (size_t)i * 192 + j);
    float* p = pool + b * 192 + j;
    atomicAdd(p + 0, v.x);
    atomicAdd(p + 1, v.y);
    atomicAdd(p + 2, v.z);
    atomicAdd(p + 3, v.w);
}

// ---------------- final MLP (single block): mean-div + 448->600->256->64 ----------------
__global__ void mlp_k(const float* __restrict__ point,
                      const float* __restrict__ l1W, const float* __restrict__ l1b,
                      const float* __restrict__ l2W, const float* __restrict__ l2b,
                      const float* __restrict__ l3W, const float* __restrict__ l3b,
                      const float* __restrict__ pool, const float* __restrict__ cnt,
                      float* __restrict__ out) {
    __shared__ float inT[448][8];
    __shared__ float h1[600][8];
    __shared__ float h2[256][8];
    int t = threadIdx.x;

    for (int idx = t; idx < 448 * 8; idx += blockDim.x) {
        int r = idx & 7, f = idx >> 3;
        float v;
        if (f < 192)       v = pool[r * 192 + f] / fmaxf(cnt[r], 1.f);
        else if (f < 384)  v = pool[1536 + r * 192 + (f - 192)] / fmaxf(cnt[8 + r], 1.f);
        else               v = point[r * 64 + (f - 384)];
        inT[f][r] = v;
    }
    __syncthreads();

    if (t < 600) {
        float acc[8];
        float b = l1b[t];
        #pragma unroll
        for (int r = 0; r < 8; r++) acc[r] = b;
        for (int f = 0; f < 448; f++) {
            float w = l1W[t * 448 + f];
            float4 p0 = *(const float4*)&inT[f][0];
            float4 p1 = *(const float4*)&inT[f][4];
            acc[0] += w * p0.x; acc[1] += w * p0.y; acc[2] += w * p0.z; acc[3] += w * p0.w;
            acc[4] += w * p1.x; acc[5] += w * p1.y; acc[6] += w * p1.z; acc[7] += w * p1.w;
        }
        #pragma unroll
        for (int r = 0; r < 8; r++) h1[t][r] = fmaxf(acc[r], 0.f);
    }
    __syncthreads();

    if (t < 256) {
        float acc[8];
        float b = l2b[t];
        #pragma unroll
        for (int r = 0; r < 8; r++) acc[r] = b;
        for (int f = 0; f < 600; f++) {
            float w = l2W[t * 600 + f];
            float4 p0 = *(const float4*)&h1[f][0];
            float4 p1 = *(const float4*)&h1[f][4];
            acc[0] += w * p0.x; acc[1] += w * p0.y; acc[2] += w * p0.z; acc[3] += w * p0.w;
            acc[4] += w * p1.x; acc[5] += w * p1.y; acc[6] += w * p1.z; acc[7] += w * p1.w;
        }
        #pragma unroll
        for (int r = 0; r < 8; r++) h2[t][r] = fmaxf(acc[r], 0.f);
    }
    __syncthreads();

    if (t < 64) {
        float acc[8];
        float b = l3b[t];
        #pragma unroll
        for (int r = 0; r < 8; r++) acc[r] = b;
        for (int f = 0; f < 256; f++) {
            float w = l3W[t * 256 + f];
            float4 p0 = *(const float4*)&h2[f][0];
            float4 p1 = *(const float4*)&h2[f][4];
            acc[0] += w * p0.x; acc[1] += w * p0.y; acc[2] += w * p0.z; acc[3] += w * p0.w;
            acc[4] += w * p1.x; acc[5] += w * p1.y; acc[6] += w * p1.z; acc[7] += w * p1.w;
        }
        #pragma unroll
        for (int r = 0; r < 8; r++) out[r * 64 + t] = acc[r];
    }
}

// ---------------- host-side branch driver ----------------
static void run_branch(const float* x0, const int* ei, int E, const int* batch, int N,
                       void* const* d_in, int wbase, float* scratch, int slot) {
    float* agg  = scratch + OFF_AGG;
    float* x1   = scratch + OFF_X1;
    float* x2   = scratch + OFF_X2;
    float* x3   = scratch + OFF_X3;
    float* wt   = scratch + OFF_WT;
    float* pool = scratch + OFF_POOL + (size_t)slot * 1536;
    float* cnt  = scratch + OFF_CNT  + (size_t)slot * 8;

    const float* W1r = (const float*)d_in[wbase + 0];
    const float* W1n = (const float*)d_in[wbase + 1];
    const float* B1  = (const float*)d_in[wbase + 2];
    const float* W2r = (const float*)d_in[wbase + 3];
    const float* W2n = (const float*)d_in[wbase + 4];
    const float* B2  = (const float*)d_in[wbase + 5];
    const float* W3r = (const float*)d_in[wbase + 6];
    const float* W3n = (const float*)d_in[wbase + 7];
    const float* B3  = (const float*)d_in[wbase + 8];

    // ---- layer 1: c=64 -> o=128
    {
        int c = 64, o = 128;
        int n4 = N * c / 4;
        zero_k<<<(n4 + 255) / 256, 256>>>((float4*)agg, n4);
        int tot = E * (c / 4);
        scatter_add<<<(tot + 255) / 256, 256>>>(x0, ei, E, c, agg);
        int wtot = 2 * c * o;
        fuse_w<<<(wtot + 255) / 256, 256>>>(W1r, W1n, wt, c, o);
        dim3 grid(o / 64, (N + 63) / 64);
        gemm_fused<<<grid, 256>>>(agg, x0, wt, B1, x1, N, c, o);
    }
    // ---- layer 2: c=128 -> o=256
    {
        int c = 128, o = 256;
        int n4 = N * c / 4;
        zero_k<<<(n4 + 255) / 256, 256>>>((float4*)agg, n4);
        int tot = E * (c / 4);
        scatter_add<<<(tot + 255) / 256, 256>>>(x1, ei, E, c, agg);
        int wtot = 2 * c * o;
        fuse_w<<<(wtot + 255) / 256, 256>>>(W2r, W2n, wt, c, o);
        dim3 grid(o / 64, (N + 63) / 64);
        gemm_fused<<<grid, 256>>>(agg, x1, wt, B2, x2, N, c, o);
    }
    // ---- layer 3: c=256 -> o=192
    {
        int c = 256, o = 192;
        int n4 = N * c / 4;
        zero_k<<<(n4 + 255) / 256, 256>>>((float4*)agg, n4);
        int tot = E * (c / 4);
        scatter_add<<<(tot + 255) / 256, 256>>>(x2, ei, E, c, agg);
        int wtot = 2 * c * o;
        fuse_w<<<(wtot + 255) / 256, 256>>>(W3r, W3n, wt, c, o);
        dim3 grid(o / 64, (N + 63) / 64);
        gemm_fused<<<grid, 256>>>(agg, x2, wt, B3, x3, N, c, o);
    }
    // ---- pooling (sums + counts; mean taken inside MLP kernel)
    pool_count<<<(N + 255) / 256, 256>>>(batch, N, cnt);
    int ptot = N * 48;
    pool_sum<<<(ptot + 255) / 256, 256>>>(x3, batch, N, pool);
}

extern "C" void kernel_launch(void* const* d_in, const int* in_sizes, int n_in,
                              void* d_out, int out_size) {
    float* scratch = nullptr;
    cudaGetSymbolAddress((void**)&scratch, d_scratch);

    // Resolve input ordering: dict order has graph_edge_index (2*800000) at slot 3;
    // reference-signature order has gW1r (8192) there.
    int GX, SX, PT, GEI, GB, SEI, SB, GW, SW, LW;
    if (n_in >= 4 && in_sizes[3] == 2 * EG) {
        GX = 0; SX = 1; PT = 2; GEI = 3; GB = 4; SEI = 5; SB = 6;
        GW = 7; SW = 16; LW = 25;
    } else {
        GX = 0; SX = 1; PT = 2; GW = 3; SW = 12; LW = 21;
        GEI = 27; GB = 28; SEI = 29; SB = 30;
    }

    // zero pooled sums + counts (3072 + 16 floats, contiguous)
    zero_k<<<(3088 / 4 + 255) / 256, 256>>>((float4*)(scratch + OFF_POOL), 3088 / 4);

    run_branch((const float*)d_in[GX], (const int*)d_in[GEI], EG,
               (const int*)d_in[GB], NG, d_in, GW, scratch, 0);
    run_branch((const float*)d_in[SX], (const int*)d_in[SEI], ES,
               (const int*)d_in[SB], NS, d_in, SW, scratch, 1);

    mlp_k<<<1, 640>>>((const float*)d_in[PT],
                      (const float*)d_in[LW + 0], (const float*)d_in[LW + 1],
                      (const float*)d_in[LW + 2], (const float*)d_in[LW + 3],
                      (const float*)d_in[LW + 4], (const float*)d_in[LW + 5],
                      scratch + OFF_POOL, scratch + OFF_CNT,
                      (float*)d_out);
}

// round 5
// speedup vs baseline: 2.4386x; 2.4386x over previous
#include <cuda_runtime.h>
#include <math.h>

#define NG 50000
#define NS 10000
#define EG 800000
#define ES 160000

// ---- scratch layout (single __device__ array, no allocations) ----
static const size_t OFF_AGG  = 0;               // up to 50000*128 = 6.4M floats
static const size_t OFF_X1   = 6400000;         // 50000*128
static const size_t OFF_X2   = 12800000;        // 50000*256
static const size_t OFF_X3   = 25600000;        // 50000*384 (xr | xn)
static const size_t OFF_WT   = 44800000;        // max 256*384
static const size_t OFF_B384 = 44900000;        // 384
static const size_t OFF_POOL = 44901000;        // 2*8*192 = 3072
static const size_t OFF_CNT  = 44904072;        // 16
__device__ float d_scratch[44905000];

__device__ __forceinline__ void red_add_v4(float* p, float4 v) {
    asm volatile("red.global.add.v4.f32 [%0], {%1, %2, %3, %4};"
                 :: "l"(p), "f"(v.x), "f"(v.y), "f"(v.z), "f"(v.w) : "memory");
}

// ---------------- zero ----------------
__global__ void zero_k(float4* p, int n4) {
    int i = blockIdx.x * blockDim.x + threadIdx.x;
    if (i < n4) p[i] = make_float4(0.f, 0.f, 0.f, 0.f);
}

// ---------------- fuse + transpose weights: Wt[k][n], k in [0,2c) ----------------
__global__ void fuse_w(const float* __restrict__ Wr, const float* __restrict__ Wn,
                       float* __restrict__ Wt, int c, int o) {
    int idx = blockIdx.x * blockDim.x + threadIdx.x;
    int total = 2 * c * o;
    if (idx >= total) return;
    int k = idx / o, n = idx - k * o;
    Wt[idx] = (k < c) ? Wr[n * c + k] : Wn[n * c + (k - c)];
}

// layer-3 variant: Wt (256 x 384), cols [0,192)=W3r^T, [192,384)=W3n^T; bias384
__global__ void fuse_w3(const float* __restrict__ Wr, const float* __restrict__ Wn,
                        const float* __restrict__ B,
                        float* __restrict__ Wt, float* __restrict__ bias384) {
    int idx = blockIdx.x * blockDim.x + threadIdx.x;
    if (idx < 384) bias384[idx] = (idx < 192) ? 0.f : B[idx - 192];
    if (idx >= 256 * 384) return;
    int k = idx / 384, n = idx - k * 384;
    Wt[idx] = (n < 192) ? Wr[n * 256 + k] : Wn[(n - 192) * 256 + k];
}

// ---------------- edge scatter-add: agg[dst] += x[src], width c ----------------
__global__ void scatter_add(const float* __restrict__ x, const int* __restrict__ ei,
                            int E, int c, float* __restrict__ agg) {
    int g = c >> 2;
    int idx = blockIdx.x * blockDim.x + threadIdx.x;
    if (idx >= E * g) return;
    int e = idx / g;
    int j = (idx - e * g) << 2;
    int src = ei[e];
    int dst = ei[E + e];
    float4 v = *(const float4*)(x + (size_t)src * c + j);
    red_add_v4(agg + (size_t)dst * c + j, v);
}

// layer-3 post-GEMM scatter: x3[dst, 192+j] += x3[src, j]  (rows are 384 wide)
__global__ void scatter3(const int* __restrict__ ei, int E, float* __restrict__ x3) {
    int idx = blockIdx.x * blockDim.x + threadIdx.x;
    if (idx >= E * 48) return;
    int e = idx / 48;
    int j = (idx - e * 48) << 2;
    int src = ei[e];
    int dst = ei[E + e];
    float4 v = *(const float4*)(x3 + (size_t)src * 384 + j);
    red_add_v4(x3 + (size_t)dst * 384 + 192 + j, v);
}

// ---------------- GEMM: out = act([A1|A2] @ Wt + bias) ----------------
// A = [A1|A2] along K (widths c each; if K==c only A1 used). Wt is K x o (k-major).
// BM=128, BN=64, TK=16, 256 threads, 8x4 micro-tile. elu: apply ELU.
__global__ void gemm2(const float* __restrict__ A1, const float* __restrict__ A2,
                      const float* __restrict__ Wt, const float* __restrict__ bias,
                      float* __restrict__ out, int Nrows, int c, int K, int o,
                      int elu) {
    __shared__ float As[16][132];   // [kk][mm]; 132*4B = 528B rows keep 16B alignment
    __shared__ float Bs[16][64];    // [kk][nn]
    int tid = threadIdx.x;
    int tx = tid & 15, ty = tid >> 4;
    int m0 = blockIdx.y * 128, n0 = blockIdx.x * 64;
    float acc[8][4] = {};

    for (int k0 = 0; k0 < K; k0 += 16) {
        const float* A = (k0 < c) ? A1 : A2;
        int col0 = (k0 < c) ? k0 : (k0 - c);
        // A tile: 128 rows x 16 k = 512 float4, 2 per thread; store transposed
        #pragma unroll
        for (int p = 0; p < 2; p++) {
            int idx = tid + p * 256;
            int m = idx >> 2;
            int kq = (idx & 3) << 2;
            float4 v = make_float4(0.f, 0.f, 0.f, 0.f);
            int gm = m0 + m;
            if (gm < Nrows) v = *(const float4*)(A + (size_t)gm * c + col0 + kq);
            As[kq + 0][m] = v.x;
            As[kq + 1][m] = v.y;
            As[kq + 2][m] = v.z;
            As[kq + 3][m] = v.w;
        }
        // B tile: 16 x 64 = 256 float4, 1 per thread
        {
            int kk = tid >> 4, nq = (tid & 15) << 2;
            *(float4*)&Bs[kk][nq] = *(const float4*)(Wt + (size_t)(k0 + kk) * o + n0 + nq);
        }
        __syncthreads();
        #pragma unroll
        for (int kk = 0; kk < 16; kk++) {
            float4 a0 = *(const float4*)&As[kk][ty * 8];
            float4 a1 = *(const float4*)&As[kk][ty * 8 + 4];
            float4 b4 = *(const float4*)&Bs[kk][tx * 4];
            float av[8] = {a0.x, a0.y, a0.z, a0.w, a1.x, a1.y, a1.z, a1.w};
            float bv[4] = {b4.x, b4.y, b4.z, b4.w};
            #pragma unroll
            for (int i = 0; i < 8; i++)
                #pragma unroll
                for (int j = 0; j < 4; j++)
                    acc[i][j] += av[i] * bv[j];
        }
        __syncthreads();
    }

    float4 bb = *(const float4*)(bias + n0 + tx * 4);
    float bvv[4] = {bb.x, bb.y, bb.z, bb.w};
    #pragma unroll
    for (int i = 0; i < 8; i++) {
        int m = m0 + ty * 8 + i;
        if (m >= Nrows) continue;
        float4 r;
        float* rp = &r.x;
        #pragma unroll
        for (int j = 0; j < 4; j++) {
            float v = acc[i][j] + bvv[j];
            if (elu) v = (v > 0.f) ? v : expm1f(v);
            rp[j] = v;
        }
        *(float4*)(out + (size_t)m * o + n0 + tx * 4) = r;
    }
}

// ---------------- pooling ----------------
__global__ void pool_count(const int* __restrict__ batch, int N, float* __restrict__ cnt) {
    int i = blockIdx.x * blockDim.x + threadIdx.x;
    if (i < N) atomicAdd(&cnt[batch[i]], 1.0f);
}

// batch is sorted: block covers 256 rows, thread t owns column t (of 192).
// Reads pre-activation x3[:,192..384), applies ELU, run-accumulates, few atomics.
__global__ void pool_sum3(const float* __restrict__ x3, const int* __restrict__ batch,
                          int N, float* __restrict__ pool) {
    int t = threadIdx.x;   // 0..191
    int r0 = blockIdx.x * 256;
    int rend = r0 + 256; if (rend > N) rend = N;
    if (r0 >= N) return;
    int cur = batch[r0];
    float acc = 0.f;
    for (int i = r0; i < rend; i++) {
        int b = batch[i];
        if (b != cur) {
            atomicAdd(&pool[cur * 192 + t], acc);
            acc = 0.f; cur = b;
        }
        float v = x3[(size_t)i * 384 + 192 + t];
        v = (v > 0.f) ? v : expm1f(v);
        acc += v;
    }
    atomicAdd(&pool[cur * 192 + t], acc);
}

// ---------------- final MLP (single block): mean-div + 448->600->256->64 ----------------
__global__ void mlp_k(const float* __restrict__ point,
                      const float* __restrict__ l1W, const float* __restrict__ l1b,
                      const float* __restrict__ l2W, const float* __restrict__ l2b,
                      const float* __restrict__ l3W, const float* __restrict__ l3b,
                      const float* __restrict__ pool, const float* __restrict__ cnt,
                      float* __restrict__ out) {
    __shared__ float inT[448][8];
    __shared__ float h1[600][8];
    __shared__ float h2[256][8];
    int t = threadIdx.x;

    for (int idx = t; idx < 448 * 8; idx += blockDim.x) {
        int r = idx & 7, f = idx >> 3;
        float v;
        if (f < 192)       v = pool[r * 192 + f] / fmaxf(cnt[r], 1.f);
        else if (f < 384)  v = pool[1536 + r * 192 + (f - 192)] / fmaxf(cnt[8 + r], 1.f);
        else               v = point[r * 64 + (f - 384)];
        inT[f][r] = v;
    }
    __syncthreads();

    if (t < 600) {
        float acc[8];
        float b = l1b[t];
        #pragma unroll
        for (int r = 0; r < 8; r++) acc[r] = b;
        for (int f = 0; f < 448; f++) {
            float w = l1W[t * 448 + f];
            float4 p0 = *(const float4*)&inT[f][0];
            float4 p1 = *(const float4*)&inT[f][4];
            acc[0] += w * p0.x; acc[1] += w * p0.y; acc[2] += w * p0.z; acc[3] += w * p0.w;
            acc[4] += w * p1.x; acc[5] += w * p1.y; acc[6] += w * p1.z; acc[7] += w * p1.w;
        }
        #pragma unroll
        for (int r = 0; r < 8; r++) h1[t][r] = fmaxf(acc[r], 0.f);
    }
    __syncthreads();

    if (t < 256) {
        float acc[8];
        float b = l2b[t];
        #pragma unroll
        for (int r = 0; r < 8; r++) acc[r] = b;
        for (int f = 0; f < 600; f++) {
            float w = l2W[t * 600 + f];
            float4 p0 = *(const float4*)&h1[f][0];
            float4 p1 = *(const float4*)&h1[f][4];
            acc[0] += w * p0.x; acc[1] += w * p0.y; acc[2] += w * p0.z; acc[3] += w * p0.w;
            acc[4] += w * p1.x; acc[5] += w * p1.y; acc[6] += w * p1.z; acc[7] += w * p1.w;
        }
        #pragma unroll
        for (int r = 0; r < 8; r++) h2[t][r] = fmaxf(acc[r], 0.f);
    }
    __syncthreads();

    if (t < 64) {
        float acc[8];
        float b = l3b[t];
        #pragma unroll
        for (int r = 0; r < 8; r++) acc[r] = b;
        for (int f = 0; f < 256; f++) {
            float w = l3W[t * 256 + f];
            float4 p0 = *(const float4*)&h2[f][0];
            float4 p1 = *(const float4*)&h2[f][4];
            acc[0] += w * p0.x; acc[1] += w * p0.y; acc[2] += w * p0.z; acc[3] += w * p0.w;
            acc[4] += w * p1.x; acc[5] += w * p1.y; acc[6] += w * p1.z; acc[7] += w * p1.w;
        }
        #pragma unroll
        for (int r = 0; r < 8; r++) out[r * 64 + t] = acc[r];
    }
}

// ---------------- host-side branch driver ----------------
static void run_branch(const float* x0, const int* ei, int E, const int* batch, int N,
                       void* const* d_in, int wbase, float* scratch, int slot) {
    float* agg  = scratch + OFF_AGG;
    float* x1   = scratch + OFF_X1;
    float* x2   = scratch + OFF_X2;
    float* x3   = scratch + OFF_X3;
    float* wt   = scratch + OFF_WT;
    float* b384 = scratch + OFF_B384;
    float* pool = scratch + OFF_POOL + (size_t)slot * 1536;
    float* cnt  = scratch + OFF_CNT  + (size_t)slot * 8;

    const float* W1r = (const float*)d_in[wbase + 0];
    const float* W1n = (const float*)d_in[wbase + 1];
    const float* B1  = (const float*)d_in[wbase + 2];
    const float* W2r = (const float*)d_in[wbase + 3];
    const float* W2n = (const float*)d_in[wbase + 4];
    const float* B2  = (const float*)d_in[wbase + 5];
    const float* W3r = (const float*)d_in[wbase + 6];
    const float* W3n = (const float*)d_in[wbase + 7];
    const float* B3  = (const float*)d_in[wbase + 8];

    // ---- layer 1: c=64 -> o=128 (pre-scatter width 64)
    {
        int c = 64, o = 128, K = 128;
        int n4 = N * c / 4;
        zero_k<<<(n4 + 255) / 256, 256>>>((float4*)agg, n4);
        int tot = E * (c / 4);
        scatter_add<<<(tot + 255) / 256, 256>>>(x0, ei, E, c, agg);
        int wtot = 2 * c * o;
        fuse_w<<<(wtot + 255) / 256, 256>>>(W1r, W1n, wt, c, o);
        dim3 grid(o / 64, (N + 127) / 128);
        gemm2<<<grid, 256>>>(agg, x0, wt, B1, x1, N, c, K, o, 1);
    }
    // ---- layer 2: c=128 -> o=256 (pre-scatter width 128)
    {
        int c = 128, o = 256, K = 256;
        int n4 = N * c / 4;
        zero_k<<<(n4 + 255) / 256, 256>>>((float4*)agg, n4);
        int tot = E * (c / 4);
        scatter_add<<<(tot + 255) / 256, 256>>>(x1, ei, E, c, agg);
        int wtot = 2 * c * o;
        fuse_w<<<(wtot + 255) / 256, 256>>>(W2r, W2n, wt, c, o);
        dim3 grid(o / 64, (N + 127) / 128);
        gemm2<<<grid, 256>>>(agg, x1, wt, B2, x2, N, c, K, o, 1);
    }
    // ---- layer 3: linearity swap — GEMM first (x2 @ [W3r^T|W3n^T]), then width-192 scatter
    {
        fuse_w3<<<(256 * 384 + 255) / 256, 256>>>(W3r, W3n, B3, wt, b384);
        dim3 grid(384 / 64, (N + 127) / 128);
        gemm2<<<grid, 256>>>(x2, x2, wt, b384, x3, N, 256, 256, 384, 0);
        int tot = E * 48;
        scatter3<<<(tot + 255) / 256, 256>>>(ei, E, x3);
    }
    // ---- pooling (ELU fused; batch sorted -> run accumulation)
    pool_count<<<(N + 255) / 256, 256>>>(batch, N, cnt);
    pool_sum3<<<(N + 255) / 256, 192>>>(x3, batch, N, pool);
}

extern "C" void kernel_launch(void* const* d_in, const int* in_sizes, int n_in,
                              void* d_out, int out_size) {
    float* scratch = nullptr;
    cudaGetSymbolAddress((void**)&scratch, d_scratch);

    // Resolve input ordering (dict order vs reference-signature order)
    int GX, SX, PT, GEI, GB, SEI, SB, GW, SW, LW;
    if (n_in >= 4 && in_sizes[3] == 2 * EG) {
        GX = 0; SX = 1; PT = 2; GEI = 3; GB = 4; SEI = 5; SB = 6;
        GW = 7; SW = 16; LW = 25;
    } else {
        GX = 0; SX = 1; PT = 2; GW = 3; SW = 12; LW = 21;
        GEI = 27; GB = 28; SEI = 29; SB = 30;
    }

    // zero pooled sums + counts (3072 + 16 floats, contiguous)
    zero_k<<<(3088 / 4 + 255) / 256, 256>>>((float4*)(scratch + OFF_POOL), 3088 / 4);

    run_branch((const float*)d_in[GX], (const int*)d_in[GEI], EG,
               (const int*)d_in[GB], NG, d_in, GW, scratch, 0);
    run_branch((const float*)d_in[SX], (const int*)d_in[SEI], ES,
               (const int*)d_in[SB], NS, d_in, SW, scratch, 1);

    mlp_k<<<1, 640>>>((const float*)d_in[PT],
                      (const float*)d_in[LW + 0], (const float*)d_in[LW + 1],
                      (const float*)d_in[LW + 2], (const float*)d_in[LW + 3],
                      (const float*)d_in[LW + 4], (const float*)d_in[LW + 5],
                      scratch + OFF_POOL, scratch + OFF_CNT,
                      (float*)d_out);
}

// round 7
// speedup vs baseline: 2.9684x; 1.2173x over previous
#include <cuda_runtime.h>
#include <math.h>
#include <stdint.h>

#define NG 50000
#define NS 10000
#define EG 800000
#define ES 160000

// ---- scratch layout (single __device__ array, no allocations) ----
static const size_t OFF_AGG  = 0;               // up to 50000*128 = 6.4M floats
static const size_t OFF_X1   = 6400000;         // 50000*128
static const size_t OFF_X2   = 12800000;        // 50000*256
static const size_t OFF_X3   = 25600000;        // 50000*384 (xr | xn)
static const size_t OFF_WT   = 44800000;        // max 256*384
static const size_t OFF_B384 = 44900000;        // 384
static const size_t OFF_POOL = 44901000;        // 2*8*192 = 3072
static const size_t OFF_CNT  = 44904072;        // 16
__device__ float d_scratch[44905000];

__device__ __forceinline__ void red_add_v4(float* p, float4 v) {
    asm volatile("red.global.add.v4.f32 [%0], {%1, %2, %3, %4};"
                 :: "l"(p), "f"(v.x), "f"(v.y), "f"(v.z), "f"(v.w) : "memory");
}

__device__ __forceinline__ uint32_t f2tf32(float f) {
    uint32_t u;
    asm("cvt.rna.tf32.f32 %0, %1;" : "=r"(u) : "f"(f));
    return u;
}

// ---------------- zero ----------------
__global__ void zero_k(float4* p, int n4) {
    int i = blockIdx.x * blockDim.x + threadIdx.x;
    if (i < n4) p[i] = make_float4(0.f, 0.f, 0.f, 0.f);
}

// ---------------- fuse + transpose weights: Wt[k][n], k in [0,2c) ----------------
__global__ void fuse_w(const float* __restrict__ Wr, const float* __restrict__ Wn,
                       float* __restrict__ Wt, int c, int o) {
    int idx = blockIdx.x * blockDim.x + threadIdx.x;
    int total = 2 * c * o;
    if (idx >= total) return;
    int k = idx / o, n = idx - k * o;
    Wt[idx] = (k < c) ? Wr[n * c + k] : Wn[n * c + (k - c)];
}

// layer-3 variant: Wt (256 x 384), cols [0,192)=W3r^T, [192,384)=W3n^T; bias384
__global__ void fuse_w3(const float* __restrict__ Wr, const float* __restrict__ Wn,
                        const float* __restrict__ B,
                        float* __restrict__ Wt, float* __restrict__ bias384) {
    int idx = blockIdx.x * blockDim.x + threadIdx.x;
    if (idx < 384) bias384[idx] = (idx < 192) ? 0.f : B[idx - 192];
    if (idx >= 256 * 384) return;
    int k = idx / 384, n = idx - k * 384;
    Wt[idx] = (n < 192) ? Wr[n * 256 + k] : Wn[(n - 192) * 256 + k];
}

// ---------------- edge scatter-add: agg[dst] += x[src], width c ----------------
__global__ void scatter_add(const float* __restrict__ x, const int* __restrict__ ei,
                            int E, int c, float* __restrict__ agg) {
    int g = c >> 2;
    int idx = blockIdx.x * blockDim.x + threadIdx.x;
    if (idx >= E * g) return;
    int e = idx / g;
    int j = (idx - e * g) << 2;
    int src = ei[e];
    int dst = ei[E + e];
    float4 v = *(const float4*)(x + (size_t)src * c + j);
    red_add_v4(agg + (size_t)dst * c + j, v);
}

// layer-3 post-GEMM scatter: x3[dst, 192+j] += x3[src, j]  (rows are 384 wide)
__global__ void scatter3(const int* __restrict__ ei, int E, float* __restrict__ x3) {
    int idx = blockIdx.x * blockDim.x + threadIdx.x;
    if (idx >= E * 48) return;
    int e = idx / 48;
    int j = (idx - e * 48) << 2;
    int src = ei[e];
    int dst = ei[E + e];
    float4 v = *(const float4*)(x3 + (size_t)src * 384 + j);
    red_add_v4(x3 + (size_t)dst * 384 + 192 + j, v);
}

// ---------------- tf32 tensor-core GEMM: out = act([A1|A2] @ Wt + bias) ----------------
// A = [A1|A2] along K (widths c each). Wt is K x o (k-major).
// BM=128, BN=64, BK=16, 256 threads = 8 warps (2M x 4N), warp tile 64x16,
// mma.sync.m16n8k8.tf32 (4 m-tiles x 2 n-tiles x 2 k-steps per BK).
__global__ void gemm_tf32(const float* __restrict__ A1, const float* __restrict__ A2,
                          const float* __restrict__ Wt, const float* __restrict__ bias,
                          float* __restrict__ out, int Nrows, int c, int K, int o,
                          int elu) {
    __shared__ uint32_t As[128][20];   // [m][k], stride 20 -> conflict-free frag loads
    __shared__ uint32_t Bs[16][68];    // [k][n], stride 68 -> conflict-free frag loads
    int tid  = threadIdx.x;
    int warp = tid >> 5;
    int lane = tid & 31;
    int wm = warp >> 2;           // 0..1 (64 rows each)
    int wn = warp & 3;            // 0..3 (16 cols each)
    int lr = lane >> 2;           // 0..7
    int lc = lane & 3;            // 0..3
    int m0 = blockIdx.y * 128, n0 = blockIdx.x * 64;

    float acc[4][2][4];
    #pragma unroll
    for (int i = 0; i < 4; i++)
        #pragma unroll
        for (int j = 0; j < 2; j++)
            #pragma unroll
            for (int q = 0; q < 4; q++) acc[i][j][q] = 0.f;

    for (int k0 = 0; k0 < K; k0 += 16) {
        const float* A = (k0 < c) ? A1 : A2;
        int col0 = (k0 < c) ? k0 : (k0 - c);
        // A tile: 128 x 16 floats = 512 float4, 2 per thread
        #pragma unroll
        for (int p = 0; p < 2; p++) {
            int idx = tid + p * 256;
            int m = idx >> 2;
            int kq = (idx & 3) << 2;
            float4 v = make_float4(0.f, 0.f, 0.f, 0.f);
            int gm = m0 + m;
            if (gm < Nrows) v = *(const float4*)(A + (size_t)gm * c + col0 + kq);
            As[m][kq + 0] = f2tf32(v.x);
            As[m][kq + 1] = f2tf32(v.y);
            As[m][kq + 2] = f2tf32(v.z);
            As[m][kq + 3] = f2tf32(v.w);
        }
        // B tile: 16 x 64 floats = 256 float4, 1 per thread
        {
            int kk = tid >> 4, nq = (tid & 15) << 2;
            float4 v = *(const float4*)(Wt + (size_t)(k0 + kk) * o + n0 + nq);
            Bs[kk][nq + 0] = f2tf32(v.x);
            Bs[kk][nq + 1] = f2tf32(v.y);
            Bs[kk][nq + 2] = f2tf32(v.z);
            Bs[kk][nq + 3] = f2tf32(v.w);
        }
        __syncthreads();

        #pragma unroll
        for (int ks = 0; ks < 2; ks++) {
            int kq = ks * 8;
            uint32_t af[4][4];
            #pragma unroll
            for (int mt = 0; mt < 4; mt++) {
                int mb = wm * 64 + mt * 16;
                af[mt][0] = As[mb + lr][kq + lc];
                af[mt][1] = As[mb + lr + 8][kq + lc];
                af[mt][2] = As[mb + lr][kq + lc + 4];
                af[mt][3] = As[mb + lr + 8][kq + lc + 4];
            }
            #pragma unroll
            for (int nt = 0; nt < 2; nt++) {
                int nb = wn * 16 + nt * 8;
                uint32_t b0 = Bs[kq + lc][nb + lr];
                uint32_t b1 = Bs[kq + lc + 4][nb + lr];
                #pragma unroll
                for (int mt = 0; mt < 4; mt++) {
                    asm volatile(
                        "mma.sync.aligned.m16n8k8.row.col.f32.tf32.tf32.f32 "
                        "{%0,%1,%2,%3}, {%4,%5,%6,%7}, {%8,%9}, {%0,%1,%2,%3};"
                        : "+f"(acc[mt][nt][0]), "+f"(acc[mt][nt][1]),
                          "+f"(acc[mt][nt][2]), "+f"(acc[mt][nt][3])
                        : "r"(af[mt][0]), "r"(af[mt][1]), "r"(af[mt][2]), "r"(af[mt][3]),
                          "r"(b0), "r"(b1));
                }
            }
        }
        __syncthreads();
    }

    // epilogue: c0,c1 -> (lr, 2lc..2lc+1); c2,c3 -> (lr+8, ...)
    int mrow0 = m0 + wm * 64;
    #pragma unroll
    for (int mt = 0; mt < 4; mt++) {
        #pragma unroll
        for (int half = 0; half < 2; half++) {
            int m = mrow0 + mt * 16 + lr + half * 8;
            if (m >= Nrows) continue;
            #pragma unroll
            for (int nt = 0; nt < 2; nt++) {
                int n = n0 + wn * 16 + nt * 8 + 2 * lc;
                float v0 = acc[mt][nt][half * 2 + 0] + bias[n];
                float v1 = acc[mt][nt][half * 2 + 1] + bias[n + 1];
                if (elu) {
                    v0 = (v0 > 0.f) ? v0 : expm1f(v0);
                    v1 = (v1 > 0.f) ? v1 : expm1f(v1);
                }
                *(float2*)(out + (size_t)m * o + n) = make_float2(v0, v1);
            }
        }
    }
}

// ---------------- pooling ----------------
__global__ void pool_count(const int* __restrict__ batch, int N, float* __restrict__ cnt) {
    int i = blockIdx.x * blockDim.x + threadIdx.x;
    if (i < N) atomicAdd(&cnt[batch[i]], 1.0f);
}

// batch sorted: block covers 256 rows, thread t owns column t (of 192).
__global__ void pool_sum3(const float* __restrict__ x3, const int* __restrict__ batch,
                          int N, float* __restrict__ pool) {
    int t = threadIdx.x;   // 0..191
    int r0 = blockIdx.x * 256;
    int rend = r0 + 256; if (rend > N) rend = N;
    if (r0 >= N) return;
    int cur = batch[r0];
    float acc = 0.f;
    for (int i = r0; i < rend; i++) {
        int b = batch[i];
        if (b != cur) {
            atomicAdd(&pool[cur * 192 + t], acc);
            acc = 0.f; cur = b;
        }
        float v = x3[(size_t)i * 384 + 192 + t];
        v = (v > 0.f) ? v : expm1f(v);
        acc += v;
    }
    atomicAdd(&pool[cur * 192 + t], acc);
}

// ---------------- final MLP (single block): mean-div + 448->600->256->64 ----------------
__global__ void mlp_k(const float* __restrict__ point,
                      const float* __restrict__ l1W, const float* __restrict__ l1b,
                      const float* __restrict__ l2W, const float* __restrict__ l2b,
                      const float* __restrict__ l3W, const float* __restrict__ l3b,
                      const float* __restrict__ pool, const float* __restrict__ cnt,
                      float* __restrict__ out) {
    __shared__ float inT[448][8];
    __shared__ float h1[600][8];
    __shared__ float h2[256][8];
    int t = threadIdx.x;

    for (int idx = t; idx < 448 * 8; idx += blockDim.x) {
        int r = idx & 7, f = idx >> 3;
        float v;
        if (f < 192)       v = pool[r * 192 + f] / fmaxf(cnt[r], 1.f);
        else if (f < 384)  v = pool[1536 + r * 192 + (f - 192)] / fmaxf(cnt[8 + r], 1.f);
        else               v = point[r * 64 + (f - 384)];
        inT[f][r] = v;
    }
    __syncthreads();

    if (t < 600) {
        float acc[8];
        float b = l1b[t];
        #pragma unroll
        for (int r = 0; r < 8; r++) acc[r] = b;
        for (int f = 0; f < 448; f++) {
            float w = l1W[t * 448 + f];
            float4 p0 = *(const float4*)&inT[f][0];
            float4 p1 = *(const float4*)&inT[f][4];
            acc[0] += w * p0.x; acc[1] += w * p0.y; acc[2] += w * p0.z; acc[3] += w * p0.w;
            acc[4] += w * p1.x; acc[5] += w * p1.y; acc[6] += w * p1.z; acc[7] += w * p1.w;
        }
        #pragma unroll
        for (int r = 0; r < 8; r++) h1[t][r] = fmaxf(acc[r], 0.f);
    }
    __syncthreads();

    if (t < 256) {
        float acc[8];
        float b = l2b[t];
        #pragma unroll
        for (int r = 0; r < 8; r++) acc[r] = b;
        for (int f = 0; f < 600; f++) {
            float w = l2W[t * 600 + f];
            float4 p0 = *(const float4*)&h1[f][0];
            float4 p1 = *(const float4*)&h1[f][4];
            acc[0] += w * p0.x; acc[1] += w * p0.y; acc[2] += w * p0.z; acc[3] += w * p0.w;
            acc[4] += w * p1.x; acc[5] += w * p1.y; acc[6] += w * p1.z; acc[7] += w * p1.w;
        }
        #pragma unroll
        for (int r = 0; r < 8; r++) h2[t][r] = fmaxf(acc[r], 0.f);
    }
    __syncthreads();

    if (t < 64) {
        float acc[8];
        float b = l3b[t];
        #pragma unroll
        for (int r = 0; r < 8; r++) acc[r] = b;
        for (int f = 0; f < 256; f++) {
            float w = l3W[t * 256 + f];
            float4 p0 = *(const float4*)&h2[f][0];
            float4 p1 = *(const float4*)&h2[f][4];
            acc[0] += w * p0.x; acc[1] += w * p0.y; acc[2] += w * p0.z; acc[3] += w * p0.w;
            acc[4] += w * p1.x; acc[5] += w * p1.y; acc[6] += w * p1.z; acc[7] += w * p1.w;
        }
        #pragma unroll
        for (int r = 0; r < 8; r++) out[r * 64 + t] = acc[r];
    }
}

// ---------------- host-side branch driver ----------------
static void run_branch(const float* x0, const int* ei, int E, const int* batch, int N,
                       void* const* d_in, int wbase, float* scratch, int slot) {
    float* agg  = scratch + OFF_AGG;
    float* x1   = scratch + OFF_X1;
    float* x2   = scratch + OFF_X2;
    float* x3   = scratch + OFF_X3;
    float* wt   = scratch + OFF_WT;
    float* b384 = scratch + OFF_B384;
    float* pool = scratch + OFF_POOL + (size_t)slot * 1536;
    float* cnt  = scratch + OFF_CNT  + (size_t)slot * 8;

    const float* W1r = (const float*)d_in[wbase + 0];
    const float* W1n = (const float*)d_in[wbase + 1];
    const float* B1  = (const float*)d_in[wbase + 2];
    const float* W2r = (const float*)d_in[wbase + 3];
    const float* W2n = (const float*)d_in[wbase + 4];
    const float* B2  = (const float*)d_in[wbase + 5];
    const float* W3r = (const float*)d_in[wbase + 6];
    const float* W3n = (const float*)d_in[wbase + 7];
    const float* B3  = (const float*)d_in[wbase + 8];

    // ---- layer 1: c=64 -> o=128 (pre-scatter width 64)
    {
        int c = 64, o = 128, K = 128;
        int n4 = N * c / 4;
        zero_k<<<(n4 + 255) / 256, 256>>>((float4*)agg, n4);
        int tot = E * (c / 4);
        scatter_add<<<(tot + 255) / 256, 256>>>(x0, ei, E, c, agg);
        int wtot = 2 * c * o;
        fuse_w<<<(wtot + 255) / 256, 256>>>(W1r, W1n, wt, c, o);
        dim3 grid(o / 64, (N + 127) / 128);
        gemm_tf32<<<grid, 256>>>(agg, x0, wt, B1, x1, N, c, K, o, 1);
    }
    // ---- layer 2: c=128 -> o=256 (pre-scatter width 128)
    {
        int c = 128, o = 256, K = 256;
        int n4 = N * c / 4;
        zero_k<<<(n4 + 255) / 256, 256>>>((float4*)agg, n4);
        int tot = E * (c / 4);
        scatter_add<<<(tot + 255) / 256, 256>>>(x1, ei, E, c, agg);
        int wtot = 2 * c * o;
        fuse_w<<<(wtot + 255) / 256, 256>>>(W2r, W2n, wt, c, o);
        dim3 grid(o / 64, (N + 127) / 128);
        gemm_tf32<<<grid, 256>>>(agg, x1, wt, B2, x2, N, c, K, o, 1);
    }
    // ---- layer 3: linearity swap — GEMM first (x2 @ [W3r^T|W3n^T]), then width-192 scatter
    {
        fuse_w3<<<(256 * 384 + 255) / 256, 256>>>(W3r, W3n, B3, wt, b384);
        dim3 grid(384 / 64, (N + 127) / 128);
        gemm_tf32<<<grid, 256>>>(x2, x2, wt, b384, x3, N, 256, 256, 384, 0);
        int tot = E * 48;
        scatter3<<<(tot + 255) / 256, 256>>>(ei, E, x3);
    }
    // ---- pooling (ELU fused; batch sorted -> run accumulation)
    pool_count<<<(N + 255) / 256, 256>>>(batch, N, cnt);
    pool_sum3<<<(N + 255) / 256, 192>>>(x3, batch, N, pool);
}

extern "C" void kernel_launch(void* const* d_in, const int* in_sizes, int n_in,
                              void* d_out, int out_size) {
    float* scratch = nullptr;
    cudaGetSymbolAddress((void**)&scratch, d_scratch);

    // Resolve input ordering (dict order vs reference-signature order)
    int GX, SX, PT, GEI, GB, SEI, SB, GW, SW, LW;
    if (n_in >= 4 && in_sizes[3] == 2 * EG) {
        GX = 0; SX = 1; PT = 2; GEI = 3; GB = 4; SEI = 5; SB = 6;
        GW = 7; SW = 16; LW = 25;
    } else {
        GX = 0; SX = 1; PT = 2; GW = 3; SW = 12; LW = 21;
        GEI = 27; GB = 28; SEI = 29; SB = 30;
    }

    // zero pooled sums + counts (3072 + 16 floats, contiguous)
    zero_k<<<(3088 / 4 + 255) / 256, 256>>>((float4*)(scratch + OFF_POOL), 3088 / 4);

    run_branch((const float*)d_in[GX], (const int*)d_in[GEI], EG,
               (const int*)d_in[GB], NG, d_in, GW, scratch, 0);
    run_branch((const float*)d_in[SX], (const int*)d_in[SEI], ES,
               (const int*)d_in[SB], NS, d_in, SW, scratch, 1);

    mlp_k<<<1, 640>>>((const float*)d_in[PT],
                      (const float*)d_in[LW + 0], (const float*)d_in[LW + 1],
                      (const float*)d_in[LW + 2], (const float*)d_in[LW + 3],
                      (const float*)d_in[LW + 4], (const float*)d_in[LW + 5],
                      scratch + OFF_POOL, scratch + OFF_CNT,
                      (float*)d_out);
}

// round 8
// speedup vs baseline: 3.3687x; 1.1349x over previous
#include <cuda_runtime.h>
#include <math.h>
#include <stdint.h>

#define NG 50000
#define NS 10000
#define EG 800000
#define ES 160000

// ---- scratch layout (single __device__ array, no allocations) ----
static const size_t AGG_G = 0;          // 50000*128 max
static const size_t AGG_S = 6400000;    // 10000*128 max (adjacent -> one zero pass)
static const size_t X1_G  = 7680000;    // 50000*128
static const size_t X1_S  = 14080000;   // 10000*128
static const size_t X2_G  = 15360000;   // 50000*256
static const size_t X2_S  = 28160000;   // 10000*256
static const size_t X3_G  = 30720000;   // 50000*384
static const size_t X3_S  = 49920000;   // 10000*384
static const size_t WT_G  = 53760000;   // 256*384 max
static const size_t WT_S  = 53860000;
static const size_t B_G   = 53960000;   // 384
static const size_t B_S   = 53960400;
static const size_t POOL  = 53960800;   // 2*8*192
static const size_t CNTO  = 53963872;   // 16
__device__ float d_scratch[53964000];

__device__ __forceinline__ void red_add_v4(float* p, float4 v) {
    asm volatile("red.global.add.v4.f32 [%0], {%1, %2, %3, %4};"
                 :: "l"(p), "f"(v.x), "f"(v.y), "f"(v.z), "f"(v.w) : "memory");
}
__device__ __forceinline__ uint32_t f2tf32(float f) {
    uint32_t u;
    asm("cvt.rna.tf32.f32 %0, %1;" : "=r"(u) : "f"(f));
    return u;
}

// ---------------- zero ----------------
__global__ void zero_k(float4* p, int n4) {
    int i = blockIdx.x * blockDim.x + threadIdx.x;
    if (i < n4) p[i] = make_float4(0.f, 0.f, 0.f, 0.f);
}

// ---------------- fuse + transpose weights (both branches) ----------------
__global__ void fuse_wc(const float* __restrict__ Wr0, const float* __restrict__ Wn0,
                        const float* __restrict__ Wr1, const float* __restrict__ Wn1,
                        float* __restrict__ Wt0, float* __restrict__ Wt1, int c, int o) {
    const float *Wr, *Wn; float* Wt;
    if (blockIdx.y == 0) { Wr = Wr0; Wn = Wn0; Wt = Wt0; }
    else                 { Wr = Wr1; Wn = Wn1; Wt = Wt1; }
    int idx = blockIdx.x * 256 + threadIdx.x;
    if (idx >= 2 * c * o) return;
    int k = idx / o, n = idx - k * o;
    Wt[idx] = (k < c) ? Wr[n * c + k] : Wn[n * c + (k - c)];
}

// layer-3: Wt (256 x 384), cols [0,192)=W3r^T, [192,384)=W3n^T; bias384
__global__ void fuse_w3c(const float* __restrict__ Wr0, const float* __restrict__ Wn0,
                         const float* __restrict__ B0,
                         const float* __restrict__ Wr1, const float* __restrict__ Wn1,
                         const float* __restrict__ B1,
                         float* __restrict__ Wt0, float* __restrict__ bias0,
                         float* __restrict__ Wt1, float* __restrict__ bias1) {
    const float *Wr, *Wn, *B; float *Wt, *bias;
    if (blockIdx.y == 0) { Wr = Wr0; Wn = Wn0; B = B0; Wt = Wt0; bias = bias0; }
    else                 { Wr = Wr1; Wn = Wn1; B = B1; Wt = Wt1; bias = bias1; }
    int idx = blockIdx.x * 256 + threadIdx.x;
    if (idx < 384) bias[idx] = (idx < 192) ? 0.f : B[idx - 192];
    if (idx >= 256 * 384) return;
    int k = idx / 384, n = idx - k * 384;
    Wt[idx] = (n < 192) ? Wr[n * 256 + k] : Wn[(n - 192) * 256 + k];
}

// ---------------- combined edge scatter-add: agg[dst] += x[src], width c ----------------
__global__ void scatter_c(const float* __restrict__ x0, const int* __restrict__ ei0, int E0,
                          float* __restrict__ agg0,
                          const float* __restrict__ x1, const int* __restrict__ ei1, int E1,
                          float* __restrict__ agg1, int c) {
    int g = c >> 2;
    int idx = blockIdx.x * 256 + threadIdx.x;
    const float* x; const int* ei; float* agg; int E, i;
    int t0 = E0 * g;
    if (idx < t0) { x = x0; ei = ei0; agg = agg0; E = E0; i = idx; }
    else {
        i = idx - t0;
        if (i >= E1 * g) return;
        x = x1; ei = ei1; agg = agg1; E = E1;
    }
    int e = i / g;
    int j = (i - e * g) << 2;
    int src = ei[e];
    int dst = ei[E + e];
    float4 v = *(const float4*)(x + (size_t)src * c + j);
    red_add_v4(agg + (size_t)dst * c + j, v);
}

// layer-3 post-GEMM scatter: x3[dst, 192+j] += x3[src, j] (rows 384 wide), both branches
__global__ void scatter3_c(const int* __restrict__ ei0, int E0, float* __restrict__ x30,
                           const int* __restrict__ ei1, int E1, float* __restrict__ x31) {
    int idx = blockIdx.x * 256 + threadIdx.x;
    const int* ei; float* x3; int E, i;
    int t0 = E0 * 48;
    if (idx < t0) { ei = ei0; x3 = x30; E = E0; i = idx; }
    else {
        i = idx - t0;
        if (i >= E1 * 48) return;
        ei = ei1; x3 = x31; E = E1;
    }
    int e = i / 48;
    int j = (i - e * 48) << 2;
    int src = ei[e];
    int dst = ei[E + e];
    float4 v = *(const float4*)(x3 + (size_t)src * 384 + j);
    red_add_v4(x3 + (size_t)dst * 384 + 192 + j, v);
}

// ---------------- tf32 GEMM, resident B + register-double-buffered A ----------------
// out = act([A1|A2] @ Wt + bias); BM=128 BN=64 BK=16; 8 warps (2Mx4N), m16n8k8.
// B slice (K x 64) converted to tf32 and held in smem for the whole block.
// One bar.sync per BK iteration.
__global__ void gemm_c(const float* __restrict__ A1g, const float* __restrict__ A2g,
                       const float* __restrict__ Wtg, const float* __restrict__ bgg,
                       float* __restrict__ outg, int N0,
                       const float* __restrict__ A1s, const float* __restrict__ A2s,
                       const float* __restrict__ Wts, const float* __restrict__ bss,
                       float* __restrict__ outs, int N1,
                       int blocks0, int c, int K, int o, int elu) {
    extern __shared__ uint32_t sm[];
    uint32_t* Bp = sm;                 // [K][68]
    uint32_t* Ap = sm + K * 68;        // [2][128][20]

    const float *A1, *A2, *Wt, *bias; float* out; int Nrows, m0;
    int by = blockIdx.y;
    if (by < blocks0) { A1 = A1g; A2 = A2g; Wt = Wtg; bias = bgg; out = outg; Nrows = N0; m0 = by * 128; }
    else              { A1 = A1s; A2 = A2s; Wt = Wts; bias = bss; out = outs; Nrows = N1; m0 = (by - blocks0) * 128; }
    int n0 = blockIdx.x * 64;
    int tid = threadIdx.x, warp = tid >> 5, lane = tid & 31;
    int wm = warp >> 2, wn = warp & 3, lr = lane >> 2, lc = lane & 3;

    // resident B: K x 64, tf32
    for (int i = tid; i < K * 16; i += 256) {
        int kk = i >> 4, nq = (i & 15) << 2;
        float4 v = *(const float4*)(Wt + (size_t)kk * o + n0 + nq);
        *(uint4*)&Bp[kk * 68 + nq] = make_uint4(f2tf32(v.x), f2tf32(v.y), f2tf32(v.z), f2tf32(v.w));
    }

    float acc[4][2][4] = {};
    int am = tid >> 2, akq = (tid & 3) << 2;
    int gm0 = m0 + am, gm1 = m0 + am + 64;
    float4 st0, st1;
    // prologue: k0 = 0 (always in A1)
    st0 = (gm0 < Nrows) ? *(const float4*)(A1 + (size_t)gm0 * c + akq) : make_float4(0.f, 0.f, 0.f, 0.f);
    st1 = (gm1 < Nrows) ? *(const float4*)(A1 + (size_t)gm1 * c + akq) : make_float4(0.f, 0.f, 0.f, 0.f);

    int iters = K >> 4;
    for (int it = 0; it < iters; it++) {
        uint32_t* Ab = Ap + (it & 1) * (128 * 20);
        *(uint4*)&Ab[am * 20 + akq]        = make_uint4(f2tf32(st0.x), f2tf32(st0.y), f2tf32(st0.z), f2tf32(st0.w));
        *(uint4*)&Ab[(am + 64) * 20 + akq] = make_uint4(f2tf32(st1.x), f2tf32(st1.y), f2tf32(st1.z), f2tf32(st1.w));
        __syncthreads();
        if (it + 1 < iters) {
            int k0 = (it + 1) << 4;
            const float* A = (k0 < c) ? A1 : A2;
            int col0 = (k0 < c) ? k0 : (k0 - c);
            st0 = (gm0 < Nrows) ? *(const float4*)(A + (size_t)gm0 * c + col0 + akq) : make_float4(0.f, 0.f, 0.f, 0.f);
            st1 = (gm1 < Nrows) ? *(const float4*)(A + (size_t)gm1 * c + col0 + akq) : make_float4(0.f, 0.f, 0.f, 0.f);
        }
        int kbase = it << 4;
        #pragma unroll
        for (int ks = 0; ks < 2; ks++) {
            int kq = ks * 8;
            uint32_t af[4][4];
            #pragma unroll
            for (int mt = 0; mt < 4; mt++) {
                int mb = wm * 64 + mt * 16;
                af[mt][0] = Ab[(mb + lr) * 20 + kq + lc];
                af[mt][1] = Ab[(mb + lr + 8) * 20 + kq + lc];
                af[mt][2] = Ab[(mb + lr) * 20 + kq + lc + 4];
                af[mt][3] = Ab[(mb + lr + 8) * 20 + kq + lc + 4];
            }
            #pragma unroll
            for (int nt = 0; nt < 2; nt++) {
                int nb = wn * 16 + nt * 8;
                uint32_t b0 = Bp[(kbase + kq + lc) * 68 + nb + lr];
                uint32_t b1 = Bp[(kbase + kq + lc + 4) * 68 + nb + lr];
                #pragma unroll
                for (int mt = 0; mt < 4; mt++) {
                    asm volatile(
                        "mma.sync.aligned.m16n8k8.row.col.f32.tf32.tf32.f32 "
                        "{%0,%1,%2,%3}, {%4,%5,%6,%7}, {%8,%9}, {%0,%1,%2,%3};"
                        : "+f"(acc[mt][nt][0]), "+f"(acc[mt][nt][1]),
                          "+f"(acc[mt][nt][2]), "+f"(acc[mt][nt][3])
                        : "r"(af[mt][0]), "r"(af[mt][1]), "r"(af[mt][2]), "r"(af[mt][3]),
                          "r"(b0), "r"(b1));
                }
            }
        }
    }

    int mrow0 = m0 + wm * 64;
    #pragma unroll
    for (int mt = 0; mt < 4; mt++) {
        #pragma unroll
        for (int half = 0; half < 2; half++) {
            int m = mrow0 + mt * 16 + lr + half * 8;
            if (m >= Nrows) continue;
            #pragma unroll
            for (int nt = 0; nt < 2; nt++) {
                int n = n0 + wn * 16 + nt * 8 + 2 * lc;
                float v0 = acc[mt][nt][half * 2 + 0] + bias[n];
                float v1 = acc[mt][nt][half * 2 + 1] + bias[n + 1];
                if (elu) {
                    v0 = (v0 > 0.f) ? v0 : expm1f(v0);
                    v1 = (v1 > 0.f) ? v1 : expm1f(v1);
                }
                *(float2*)(out + (size_t)m * o + n) = make_float2(v0, v1);
            }
        }
    }
}

// ---------------- pooling (both branches, count fused; batch sorted) ----------------
__global__ void pool_c(const float* __restrict__ x3a, const int* __restrict__ ba,
                       float* __restrict__ pa, float* __restrict__ ca, int N0, int blocks0,
                       const float* __restrict__ x3b, const int* __restrict__ bb,
                       float* __restrict__ pb, float* __restrict__ cb, int N1) {
    const float* x3; const int* batch; float* pool; float* cnt; int N, blk;
    if ((int)blockIdx.x < blocks0) { x3 = x3a; batch = ba; pool = pa; cnt = ca; N = N0; blk = blockIdx.x; }
    else { x3 = x3b; batch = bb; pool = pb; cnt = cb; N = N1; blk = blockIdx.x - blocks0; }
    int t = threadIdx.x;   // 0..191
    int r0 = blk * 256;
    int rend = r0 + 256; if (rend > N) rend = N;
    if (r0 >= N) return;
    int cur = batch[r0];
    float acc = 0.f, cacc = 0.f;
    for (int i = r0; i < rend; i++) {
        int b = batch[i];
        if (b != cur) {
            atomicAdd(&pool[cur * 192 + t], acc);
            if (t == 0) atomicAdd(&cnt[cur], cacc);
            acc = 0.f; cacc = 0.f; cur = b;
        }
        float v = x3[(size_t)i * 384 + 192 + t];
        v = (v > 0.f) ? v : expm1f(v);
        acc += v; cacc += 1.f;
    }
    atomicAdd(&pool[cur * 192 + t], acc);
    if (t == 0) atomicAdd(&cnt[cur], cacc);
}

// ---------------- final MLP (single block): mean-div + 448->600->256->64 ----------------
__global__ void mlp_k(const float* __restrict__ point,
                      const float* __restrict__ l1W, const float* __restrict__ l1b,
                      const float* __restrict__ l2W, const float* __restrict__ l2b,
                      const float* __restrict__ l3W, const float* __restrict__ l3b,
                      const float* __restrict__ pool, const float* __restrict__ cnt,
                      float* __restrict__ out) {
    __shared__ float inT[448][8];
    __shared__ float h1[600][8];
    __shared__ float h2[256][8];
    int t = threadIdx.x;

    for (int idx = t; idx < 448 * 8; idx += blockDim.x) {
        int r = idx & 7, f = idx >> 3;
        float v;
        if (f < 192)       v = pool[r * 192 + f] / fmaxf(cnt[r], 1.f);
        else if (f < 384)  v = pool[1536 + r * 192 + (f - 192)] / fmaxf(cnt[8 + r], 1.f);
        else               v = point[r * 64 + (f - 384)];
        inT[f][r] = v;
    }
    __syncthreads();

    if (t < 600) {
        float acc[8];
        float b = l1b[t];
        #pragma unroll
        for (int r = 0; r < 8; r++) acc[r] = b;
        for (int f = 0; f < 448; f++) {
            float w = l1W[t * 448 + f];
            float4 p0 = *(const float4*)&inT[f][0];
            float4 p1 = *(const float4*)&inT[f][4];
            acc[0] += w * p0.x; acc[1] += w * p0.y; acc[2] += w * p0.z; acc[3] += w * p0.w;
            acc[4] += w * p1.x; acc[5] += w * p1.y; acc[6] += w * p1.z; acc[7] += w * p1.w;
        }
        #pragma unroll
        for (int r = 0; r < 8; r++) h1[t][r] = fmaxf(acc[r], 0.f);
    }
    __syncthreads();

    if (t < 256) {
        float acc[8];
        float b = l2b[t];
        #pragma unroll
        for (int r = 0; r < 8; r++) acc[r] = b;
        for (int f = 0; f < 600; f++) {
            float w = l2W[t * 600 + f];
            float4 p0 = *(const float4*)&h1[f][0];
            float4 p1 = *(const float4*)&h1[f][4];
            acc[0] += w * p0.x; acc[1] += w * p0.y; acc[2] += w * p0.z; acc[3] += w * p0.w;
            acc[4] += w * p1.x; acc[5] += w * p1.y; acc[6] += w * p1.z; acc[7] += w * p1.w;
        }
        #pragma unroll
        for (int r = 0; r < 8; r++) h2[t][r] = fmaxf(acc[r], 0.f);
    }
    __syncthreads();

    if (t < 64) {
        float acc[8];
        float b = l3b[t];
        #pragma unroll
        for (int r = 0; r < 8; r++) acc[r] = b;
        for (int f = 0; f < 256; f++) {
            float w = l3W[t * 256 + f];
            float4 p0 = *(const float4*)&h2[f][0];
            float4 p1 = *(const float4*)&h2[f][4];
            acc[0] += w * p0.x; acc[1] += w * p0.y; acc[2] += w * p0.z; acc[3] += w * p0.w;
            acc[4] += w * p1.x; acc[5] += w * p1.y; acc[6] += w * p1.z; acc[7] += w * p1.w;
        }
        #pragma unroll
        for (int r = 0; r < 8; r++) out[r * 64 + t] = acc[r];
    }
}

extern "C" void kernel_launch(void* const* d_in, const int* in_sizes, int n_in,
                              void* d_out, int out_size) {
    float* scratch = nullptr;
    cudaGetSymbolAddress((void**)&scratch, d_scratch);
    cudaFuncSetAttribute(gemm_c, cudaFuncAttributeMaxDynamicSharedMemorySize, 90112);

    // Resolve input ordering (dict order vs reference-signature order)
    int GX, SX, PT, GEI, GB, SEI, SB, GW, SW, LW;
    if (n_in >= 4 && in_sizes[3] == 2 * EG) {
        GX = 0; SX = 1; PT = 2; GEI = 3; GB = 4; SEI = 5; SB = 6;
        GW = 7; SW = 16; LW = 25;
    } else {
        GX = 0; SX = 1; PT = 2; GW = 3; SW = 12; LW = 21;
        GEI = 27; GB = 28; SEI = 29; SB = 30;
    }

    const float* x0g = (const float*)d_in[GX];
    const float* x0s = (const float*)d_in[SX];
    const int* eig = (const int*)d_in[GEI];
    const int* eis = (const int*)d_in[SEI];
    const int* bag = (const int*)d_in[GB];
    const int* bas = (const int*)d_in[SB];

    float* aggg = scratch + AGG_G;  float* aggs = scratch + AGG_S;
    float* x1g  = scratch + X1_G;   float* x1s  = scratch + X1_S;
    float* x2g  = scratch + X2_G;   float* x2s  = scratch + X2_S;
    float* x3g  = scratch + X3_G;   float* x3s  = scratch + X3_S;
    float* wtg  = scratch + WT_G;   float* wts  = scratch + WT_S;
    float* b3g  = scratch + B_G;    float* b3s  = scratch + B_S;
    float* pool = scratch + POOL;
    float* cnt  = scratch + CNTO;

    int b0 = (NG + 127) / 128, b1 = (NS + 127) / 128;

    // zero pooled sums + counts (3072 + 16 floats, contiguous)
    zero_k<<<(772 + 255) / 256, 256>>>((float4*)pool, 772);

    // ---- layer 1: c=64 -> o=128
    {
        int c = 64, o = 128, K = 128;
        int nz = (6400000 + 10000 * c) / 4;
        zero_k<<<(nz + 255) / 256, 256>>>((float4*)scratch, nz);
        int tot = (EG + ES) * (c / 4);
        scatter_c<<<(tot + 255) / 256, 256>>>(x0g, eig, EG, aggg, x0s, eis, ES, aggs, c);
        fuse_wc<<<dim3((2 * c * o + 255) / 256, 2), 256>>>(
            (const float*)d_in[GW + 0], (const float*)d_in[GW + 1],
            (const float*)d_in[SW + 0], (const float*)d_in[SW + 1], wtg, wts, c, o);
        size_t smem = (size_t)(K * 68 + 2 * 128 * 20) * 4;
        gemm_c<<<dim3(o / 64, b0 + b1), 256, smem>>>(
            aggg, x0g, wtg, (const float*)d_in[GW + 2], x1g, NG,
            aggs, x0s, wts, (const float*)d_in[SW + 2], x1s, NS,
            b0, c, K, o, 1);
    }
    // ---- layer 2: c=128 -> o=256
    {
        int c = 128, o = 256, K = 256;
        int nz = (6400000 + 10000 * c) / 4;
        zero_k<<<(nz + 255) / 256, 256>>>((float4*)scratch, nz);
        int tot = (EG + ES) * (c / 4);
        scatter_c<<<(tot + 255) / 256, 256>>>(x1g, eig, EG, aggg, x1s, eis, ES, aggs, c);
        fuse_wc<<<dim3((2 * c * o + 255) / 256, 2), 256>>>(
            (const float*)d_in[GW + 3], (const float*)d_in[GW + 4],
            (const float*)d_in[SW + 3], (const float*)d_in[SW + 4], wtg, wts, c, o);
        size_t smem = (size_t)(K * 68 + 2 * 128 * 20) * 4;
        gemm_c<<<dim3(o / 64, b0 + b1), 256, smem>>>(
            aggg, x1g, wtg, (const float*)d_in[GW + 5], x2g, NG,
            aggs, x1s, wts, (const float*)d_in[SW + 5], x2s, NS,
            b0, c, K, o, 1);
    }
    // ---- layer 3: GEMM first (linearity swap), then width-192 scatter, then pool
    {
        fuse_w3c<<<dim3((256 * 384 + 255) / 256, 2), 256>>>(
            (const float*)d_in[GW + 6], (const float*)d_in[GW + 7], (const float*)d_in[GW + 8],
            (const float*)d_in[SW + 6], (const float*)d_in[SW + 7], (const float*)d_in[SW + 8],
            wtg, b3g, wts, b3s);
        size_t smem = (size_t)(256 * 68 + 2 * 128 * 20) * 4;
        gemm_c<<<dim3(384 / 64, b0 + b1), 256, smem>>>(
            x2g, x2g, wtg, b3g, x3g, NG,
            x2s, x2s, wts, b3s, x3s, NS,
            b0, 256, 256, 384, 0);
        int tot = (EG + ES) * 48;
        scatter3_c<<<(tot + 255) / 256, 256>>>(eig, EG, x3g, eis, ES, x3s);
        int pb0 = (NG + 255) / 256, pb1 = (NS + 255) / 256;
        pool_c<<<pb0 + pb1, 192>>>(x3g, bag, pool, cnt, NG, pb0,
                                   x3s, bas, pool + 1536, cnt + 8, NS);
    }

    mlp_k<<<1, 640>>>((const float*)d_in[PT],
                      (const float*)d_in[LW + 0], (const float*)d_in[LW + 1],
                      (const float*)d_in[LW + 2], (const float*)d_in[LW + 3],
                      (const float*)d_in[LW + 4], (const float*)d_in[LW + 5],
                      pool, cnt, (float*)d_out);
}

// round 9
// speedup vs baseline: 3.6165x; 1.0735x over previous
#include <cuda_runtime.h>
#include <math.h>
#include <stdint.h>

#define NG 50000
#define NS 10000
#define EG 800000
#define ES 160000

// ---- scratch layout (single __device__ array, no allocations) ----
static const size_t AGG_G = 0;          // 50000*128 max
static const size_t AGG_S = 6400000;
static const size_t X1_G  = 7680000;    // 50000*128
static const size_t X1_S  = 14080000;
static const size_t X2_G  = 15360000;   // 50000*256
static const size_t X2_S  = 28160000;
static const size_t X3_G  = 30720000;   // 50000*384
static const size_t X3_S  = 49920000;
static const size_t WT_G  = 53760000;   // 256*384 max
static const size_t WT_S  = 53860000;
static const size_t B_G   = 53960000;   // 384
static const size_t B_S   = 53960400;
static const size_t POOL  = 53960800;   // 2*8*192
static const size_t CNTO  = 53963872;   // 16
// ---- CSR structures (ints stored in float scratch) ----
static const size_t DEG_G  = 53963904;  // 50001
static const size_t DEG_S  = 54013905;  // 10001 (contiguous with DEG_G for one zero pass)
static const size_t PTR_G  = 54023906;  // 50001
static const size_t PTR_S  = 54073907;  // 10001
static const size_t FILL_G = 54083908;  // 50000
static const size_t FILL_S = 54133908;  // 10000
static const size_t SS_G   = 54143908;  // 800000
static const size_t SS_S   = 54943908;  // 160000
__device__ float d_scratch[55104000];

__device__ __forceinline__ uint32_t f2tf32(float f) {
    uint32_t u;
    asm("cvt.rna.tf32.f32 %0, %1;" : "=r"(u) : "f"(f));
    return u;
}
__device__ __forceinline__ void ldsm_x4(uint32_t& r0, uint32_t& r1, uint32_t& r2, uint32_t& r3, uint32_t addr) {
    asm volatile("ldmatrix.sync.aligned.m8n8.x4.shared.b16 {%0,%1,%2,%3}, [%4];"
                 : "=r"(r0), "=r"(r1), "=r"(r2), "=r"(r3) : "r"(addr));
}
__device__ __forceinline__ void ldsm_x2(uint32_t& r0, uint32_t& r1, uint32_t addr) {
    asm volatile("ldmatrix.sync.aligned.m8n8.x2.shared.b16 {%0,%1}, [%2];"
                 : "=r"(r0), "=r"(r1) : "r"(addr));
}

// ---------------- zero ----------------
__global__ void zero_k(float4* p, int n4) {
    int i = blockIdx.x * blockDim.x + threadIdx.x;
    if (i < n4) p[i] = make_float4(0.f, 0.f, 0.f, 0.f);
}

// ---------------- CSR build: histogram, scan, fill ----------------
__global__ void hist_c(const int* __restrict__ ei0, int E0, int* __restrict__ deg0,
                       const int* __restrict__ ei1, int E1, int* __restrict__ deg1) {
    int i = blockIdx.x * 256 + threadIdx.x;
    if (i < E0) atomicAdd(&deg0[ei0[E0 + i]], 1);
    else {
        int j = i - E0;
        if (j < E1) atomicAdd(&deg1[ei1[E1 + j]], 1);
    }
}

__global__ void scan2(const int* __restrict__ dga, int* __restrict__ pta, int* __restrict__ fla, int Na,
                      const int* __restrict__ dgb, int* __restrict__ ptb, int* __restrict__ flb, int Nb) {
    const int* deg; int* ptr; int* fill; int N;
    if (blockIdx.x == 0) { deg = dga; ptr = pta; fill = fla; N = Na; }
    else                 { deg = dgb; ptr = ptb; fill = flb; N = Nb; }
    __shared__ int part[1024];
    int t = threadIdx.x;
    int chunk = (N + 1023) >> 10;
    int base = t * chunk;
    int s = 0;
    for (int i = 0; i < chunk; i++) {
        int idx = base + i;
        if (idx < N) s += deg[idx];
    }
    part[t] = s;
    __syncthreads();
    for (int off = 1; off < 1024; off <<= 1) {
        int v = (t >= off) ? part[t - off] : 0;
        __syncthreads();
        part[t] += v;
        __syncthreads();
    }
    int run = (t > 0) ? part[t - 1] : 0;
    for (int i = 0; i < chunk; i++) {
        int idx = base + i;
        if (idx < N) {
            ptr[idx] = run;
            fill[idx] = run;
            run += deg[idx];
        }
    }
    if (t == 1023) ptr[N] = part[1023];
}

__global__ void fill_c(const int* __restrict__ ei0, int E0, int* __restrict__ fill0, int* __restrict__ ss0,
                       const int* __restrict__ ei1, int E1, int* __restrict__ fill1, int* __restrict__ ss1) {
    int i = blockIdx.x * 256 + threadIdx.x;
    if (i < E0) {
        int dst = ei0[E0 + i];
        int p = atomicAdd(&fill0[dst], 1);
        ss0[p] = ei0[i];
    } else {
        int j = i - E0;
        if (j >= E1) return;
        int dst = ei1[E1 + j];
        int p = atomicAdd(&fill1[dst], 1);
        ss1[p] = ei1[j];
    }
}

// ---------------- CSR gather: agg[n] = sum over incoming edges of x[src] ----------------
__global__ void gather_c(const float* __restrict__ x0, const int* __restrict__ ptr0,
                         const int* __restrict__ ss0, float* __restrict__ agg0, int N0,
                         const float* __restrict__ x1, const int* __restrict__ ptr1,
                         const int* __restrict__ ss1, float* __restrict__ agg1, int N1,
                         int c, int shift) {
    int idx = blockIdx.x * 256 + threadIdx.x;
    const float* x; const int* ptr; const int* ss; float* agg; int i;
    int t0 = N0 << shift;
    if (idx < t0) { x = x0; ptr = ptr0; ss = ss0; agg = agg0; i = idx; }
    else {
        i = idx - t0;
        if (i >= (N1 << shift)) return;
        x = x1; ptr = ptr1; ss = ss1; agg = agg1;
    }
    int n = i >> shift;
    int q = (i & ((1 << shift) - 1)) << 2;
    int e0 = ptr[n], e1 = ptr[n + 1];
    float4 acc = make_float4(0.f, 0.f, 0.f, 0.f);
    for (int e = e0; e < e1; e++) {
        int s = ss[e];
        float4 v = *(const float4*)(x + (size_t)s * c + q);
        acc.x += v.x; acc.y += v.y; acc.z += v.z; acc.w += v.w;
    }
    *(float4*)(agg + (size_t)n * c + q) = acc;
}

// layer-3 gather: x3[n,192+q] += sum x3[src,q]  (rows 384 wide; in-place, disjoint col ranges)
__global__ void gather3_c(const int* __restrict__ ptr0, const int* __restrict__ ss0,
                          float* __restrict__ x30, int N0,
                          const int* __restrict__ ptr1, const int* __restrict__ ss1,
                          float* __restrict__ x31, int N1) {
    int idx = blockIdx.x * 256 + threadIdx.x;
    const int* ptr; const int* ss; float* x3; int i;
    int t0 = N0 * 48;
    if (idx < t0) { ptr = ptr0; ss = ss0; x3 = x30; i = idx; }
    else {
        i = idx - t0;
        if (i >= N1 * 48) return;
        ptr = ptr1; ss = ss1; x3 = x31;
    }
    int n = i / 48;
    int q = (i - n * 48) << 2;
    int e0 = ptr[n], e1 = ptr[n + 1];
    float4 acc = *(const float4*)(x3 + (size_t)n * 384 + 192 + q);
    for (int e = e0; e < e1; e++) {
        int s = ss[e];
        float4 v = *(const float4*)(x3 + (size_t)s * 384 + q);
        acc.x += v.x; acc.y += v.y; acc.z += v.z; acc.w += v.w;
    }
    *(float4*)(x3 + (size_t)n * 384 + 192 + q) = acc;
}

// ---------------- fuse + transpose weights (both branches) ----------------
__global__ void fuse_wc(const float* __restrict__ Wr0, const float* __restrict__ Wn0,
                        const float* __restrict__ Wr1, const float* __restrict__ Wn1,
                        float* __restrict__ Wt0, float* __restrict__ Wt1, int c, int o) {
    const float *Wr, *Wn; float* Wt;
    if (blockIdx.y == 0) { Wr = Wr0; Wn = Wn0; Wt = Wt0; }
    else                 { Wr = Wr1; Wn = Wn1; Wt = Wt1; }
    int idx = blockIdx.x * 256 + threadIdx.x;
    if (idx >= 2 * c * o) return;
    int k = idx / o, n = idx - k * o;
    Wt[idx] = (k < c) ? Wr[n * c + k] : Wn[n * c + (k - c)];
}

__global__ void fuse_w3c(const float* __restrict__ Wr0, const float* __restrict__ Wn0,
                         const float* __restrict__ B0,
                         const float* __restrict__ Wr1, const float* __restrict__ Wn1,
                         const float* __restrict__ B1,
                         float* __restrict__ Wt0, float* __restrict__ bias0,
                         float* __restrict__ Wt1, float* __restrict__ bias1) {
    const float *Wr, *Wn, *B; float *Wt, *bias;
    if (blockIdx.y == 0) { Wr = Wr0; Wn = Wn0; B = B0; Wt = Wt0; bias = bias0; }
    else                 { Wr = Wr1; Wn = Wn1; B = B1; Wt = Wt1; bias = bias1; }
    int idx = blockIdx.x * 256 + threadIdx.x;
    if (idx < 384) bias[idx] = (idx < 192) ? 0.f : B[idx - 192];
    if (idx >= 256 * 384) return;
    int k = idx / 384, n = idx - k * 384;
    Wt[idx] = (n < 192) ? Wr[n * 256 + k] : Wn[(n - 192) * 256 + k];
}

// ---------------- tf32 GEMM: resident n-major B + reg-double-buffered A + ldmatrix ----------------
// out = act([A1|A2] @ Wt + bias); BM=128 BN=64 BK=16; 8 warps (2Mx4N), m16n8k8.
__global__ void gemm_c(const float* __restrict__ A1g, const float* __restrict__ A2g,
                       const float* __restrict__ Wtg, const float* __restrict__ bgg,
                       float* __restrict__ outg, int N0,
                       const float* __restrict__ A1s, const float* __restrict__ A2s,
                       const float* __restrict__ Wts, const float* __restrict__ bss,
                       float* __restrict__ outs, int N1,
                       int blocks0, int c, int K, int o, int elu) {
    extern __shared__ uint32_t sm[];
    int bs = K + 4;
    uint32_t* Bp = sm;                 // [64][K+4]  (n-major, tf32)
    uint32_t* Ap = sm + 64 * bs;       // [2][128][20]

    const float *A1, *A2, *Wt, *bias; float* out; int Nrows, m0;
    int by = blockIdx.y;
    if (by < blocks0) { A1 = A1g; A2 = A2g; Wt = Wtg; bias = bgg; out = outg; Nrows = N0; m0 = by * 128; }
    else              { A1 = A1s; A2 = A2s; Wt = Wts; bias = bss; out = outs; Nrows = N1; m0 = (by - blocks0) * 128; }
    int n0 = blockIdx.x * 64;
    int tid = threadIdx.x, warp = tid >> 5, lane = tid & 31;
    int wm = warp >> 2, wn = warp & 3, lr = lane >> 2, lc = lane & 3;

    // resident B: read Wt[k][n] coalesced, store transposed [n][k] as tf32
    for (int i = tid; i < K * 16; i += 256) {
        int kk = i >> 4, nq = (i & 15) << 2;
        float4 v = *(const float4*)(Wt + (size_t)kk * o + n0 + nq);
        Bp[(nq + 0) * bs + kk] = f2tf32(v.x);
        Bp[(nq + 1) * bs + kk] = f2tf32(v.y);
        Bp[(nq + 2) * bs + kk] = f2tf32(v.z);
        Bp[(nq + 3) * bs + kk] = f2tf32(v.w);
    }

    uint32_t b_base = (uint32_t)__cvta_generic_to_shared(Bp);
    uint32_t a_base0 = (uint32_t)__cvta_generic_to_shared(Ap);
    uint32_t a_base1 = a_base0 + 128 * 20 * 4;
    int arow = lane & 15, acolo = (lane >> 4) << 2;     // ldmatrix.x4 lane addressing
    int brow = lane & 7,  bcolo = ((lane >> 3) & 1) << 2; // ldmatrix.x2 lane addressing

    float acc[4][2][4] = {};
    int am = tid >> 2, akq = (tid & 3) << 2;
    int gm0 = m0 + am, gm1 = m0 + am + 64;
    float4 st0, st1;
    st0 = (gm0 < Nrows) ? *(const float4*)(A1 + (size_t)gm0 * c + akq) : make_float4(0.f, 0.f, 0.f, 0.f);
    st1 = (gm1 < Nrows) ? *(const float4*)(A1 + (size_t)gm1 * c + akq) : make_float4(0.f, 0.f, 0.f, 0.f);

    int iters = K >> 4;
    for (int it = 0; it < iters; it++) {
        uint32_t* Ab = Ap + (it & 1) * (128 * 20);
        uint32_t a_base = (it & 1) ? a_base1 : a_base0;
        *(uint4*)&Ab[am * 20 + akq]        = make_uint4(f2tf32(st0.x), f2tf32(st0.y), f2tf32(st0.z), f2tf32(st0.w));
        *(uint4*)&Ab[(am + 64) * 20 + akq] = make_uint4(f2tf32(st1.x), f2tf32(st1.y), f2tf32(st1.z), f2tf32(st1.w));
        __syncthreads();
        if (it + 1 < iters) {
            int k0 = (it + 1) << 4;
            const float* A = (k0 < c) ? A1 : A2;
            int col0 = (k0 < c) ? k0 : (k0 - c);
            st0 = (gm0 < Nrows) ? *(const float4*)(A + (size_t)gm0 * c + col0 + akq) : make_float4(0.f, 0.f, 0.f, 0.f);
            st1 = (gm1 < Nrows) ? *(const float4*)(A + (size_t)gm1 * c + col0 + akq) : make_float4(0.f, 0.f, 0.f, 0.f);
        }
        int kbase = it << 4;
        #pragma unroll
        for (int ks = 0; ks < 2; ks++) {
            int kq = ks << 3;
            uint32_t af[4][4];
            #pragma unroll
            for (int mt = 0; mt < 4; mt++) {
                int mb = wm * 64 + mt * 16;
                uint32_t addr = a_base + (uint32_t)(((mb + arow) * 20 + kq + acolo) << 2);
                ldsm_x4(af[mt][0], af[mt][1], af[mt][2], af[mt][3], addr);
            }
            uint32_t bf[2][2];
            #pragma unroll
            for (int nt = 0; nt < 2; nt++) {
                int nb = wn * 16 + nt * 8;
                uint32_t addr = b_base + (uint32_t)(((nb + brow) * bs + kbase + kq + bcolo) << 2);
                ldsm_x2(bf[nt][0], bf[nt][1], addr);
            }
            #pragma unroll
            for (int nt = 0; nt < 2; nt++) {
                #pragma unroll
                for (int mt = 0; mt < 4; mt++) {
                    asm volatile(
                        "mma.sync.aligned.m16n8k8.row.col.f32.tf32.tf32.f32 "
                        "{%0,%1,%2,%3}, {%4,%5,%6,%7}, {%8,%9}, {%0,%1,%2,%3};"
                        : "+f"(acc[mt][nt][0]), "+f"(acc[mt][nt][1]),
                          "+f"(acc[mt][nt][2]), "+f"(acc[mt][nt][3])
                        : "r"(af[mt][0]), "r"(af[mt][1]), "r"(af[mt][2]), "r"(af[mt][3]),
                          "r"(bf[nt][0]), "r"(bf[nt][1]));
                }
            }
        }
    }

    int mrow0 = m0 + wm * 64;
    #pragma unroll
    for (int mt = 0; mt < 4; mt++) {
        #pragma unroll
        for (int half = 0; half < 2; half++) {
            int m = mrow0 + mt * 16 + lr + half * 8;
            if (m >= Nrows) continue;
            #pragma unroll
            for (int nt = 0; nt < 2; nt++) {
                int n = n0 + wn * 16 + nt * 8 + 2 * lc;
                float v0 = acc[mt][nt][half * 2 + 0] + bias[n];
                float v1 = acc[mt][nt][half * 2 + 1] + bias[n + 1];
                if (elu) {
                    v0 = (v0 > 0.f) ? v0 : expm1f(v0);
                    v1 = (v1 > 0.f) ? v1 : expm1f(v1);
                }
                *(float2*)(out + (size_t)m * o + n) = make_float2(v0, v1);
            }
        }
    }
}

// ---------------- pooling (both branches, count fused; batch sorted) ----------------
__global__ void pool_c(const float* __restrict__ x3a, const int* __restrict__ ba,
                       float* __restrict__ pa, float* __restrict__ ca, int N0, int blocks0,
                       const float* __restrict__ x3b, const int* __restrict__ bb,
                       float* __restrict__ pb, float* __restrict__ cb, int N1) {
    const float* x3; const int* batch; float* pool; float* cnt; int N, blk;
    if ((int)blockIdx.x < blocks0) { x3 = x3a; batch = ba; pool = pa; cnt = ca; N = N0; blk = blockIdx.x; }
    else { x3 = x3b; batch = bb; pool = pb; cnt = cb; N = N1; blk = blockIdx.x - blocks0; }
    int t = threadIdx.x;   // 0..191
    int r0 = blk * 256;
    int rend = r0 + 256; if (rend > N) rend = N;
    if (r0 >= N) return;
    int cur = batch[r0];
    float acc = 0.f, cacc = 0.f;
    for (int i = r0; i < rend; i++) {
        int b = batch[i];
        if (b != cur) {
            atomicAdd(&pool[cur * 192 + t], acc);
            if (t == 0) atomicAdd(&cnt[cur], cacc);
            acc = 0.f; cacc = 0.f; cur = b;
        }
        float v = x3[(size_t)i * 384 + 192 + t];
        v = (v > 0.f) ? v : expm1f(v);
        acc += v; cacc += 1.f;
    }
    atomicAdd(&pool[cur * 192 + t], acc);
    if (t == 0) atomicAdd(&cnt[cur], cacc);
}

// ---------------- final MLP (single block): mean-div + 448->600->256->64 ----------------
__global__ void mlp_k(const float* __restrict__ point,
                      const float* __restrict__ l1W, const float* __restrict__ l1b,
                      const float* __restrict__ l2W, const float* __restrict__ l2b,
                      const float* __restrict__ l3W, const float* __restrict__ l3b,
                      const float* __restrict__ pool, const float* __restrict__ cnt,
                      float* __restrict__ out) {
    __shared__ float inT[448][8];
    __shared__ float h1[600][8];
    __shared__ float h2[256][8];
    int t = threadIdx.x;

    for (int idx = t; idx < 448 * 8; idx += blockDim.x) {
        int r = idx & 7, f = idx >> 3;
        float v;
        if (f < 192)       v = pool[r * 192 + f] / fmaxf(cnt[r], 1.f);
        else if (f < 384)  v = pool[1536 + r * 192 + (f - 192)] / fmaxf(cnt[8 + r], 1.f);
        else               v = point[r * 64 + (f - 384)];
        inT[f][r] = v;
    }
    __syncthreads();

    if (t < 600) {
        float acc[8];
        float b = l1b[t];
        #pragma unroll
        for (int r = 0; r < 8; r++) acc[r] = b;
        for (int f = 0; f < 448; f++) {
            float w = l1W[t * 448 + f];
            float4 p0 = *(const float4*)&inT[f][0];
            float4 p1 = *(const float4*)&inT[f][4];
            acc[0] += w * p0.x; acc[1] += w * p0.y; acc[2] += w * p0.z; acc[3] += w * p0.w;
            acc[4] += w * p1.x; acc[5] += w * p1.y; acc[6] += w * p1.z; acc[7] += w * p1.w;
        }
        #pragma unroll
        for (int r = 0; r < 8; r++) h1[t][r] = fmaxf(acc[r], 0.f);
    }
    __syncthreads();

    if (t < 256) {
        float acc[8];
        float b = l2b[t];
        #pragma unroll
        for (int r = 0; r < 8; r++) acc[r] = b;
        for (int f = 0; f < 600; f++) {
            float w = l2W[t * 600 + f];
            float4 p0 = *(const float4*)&h1[f][0];
            float4 p1 = *(const float4*)&h1[f][4];
            acc[0] += w * p0.x; acc[1] += w * p0.y; acc[2] += w * p0.z; acc[3] += w * p0.w;
            acc[4] += w * p1.x; acc[5] += w * p1.y; acc[6] += w * p1.z; acc[7] += w * p1.w;
        }
        #pragma unroll
        for (int r = 0; r < 8; r++) h2[t][r] = fmaxf(acc[r], 0.f);
    }
    __syncthreads();

    if (t < 64) {
        float acc[8];
        float b = l3b[t];
        #pragma unroll
        for (int r = 0; r < 8; r++) acc[r] = b;
        for (int f = 0; f < 256; f++) {
            float w = l3W[t * 256 + f];
            float4 p0 = *(const float4*)&h2[f][0];
            float4 p1 = *(const float4*)&h2[f][4];
            acc[0] += w * p0.x; acc[1] += w * p0.y; acc[2] += w * p0.z; acc[3] += w * p0.w;
            acc[4] += w * p1.x; acc[5] += w * p1.y; acc[6] += w * p1.z; acc[7] += w * p1.w;
        }
        #pragma unroll
        for (int r = 0; r < 8; r++) out[r * 64 + t] = acc[r];
    }
}

extern "C" void kernel_launch(void* const* d_in, const int* in_sizes, int n_in,
                              void* d_out, int out_size) {
    float* scratch = nullptr;
    cudaGetSymbolAddress((void**)&scratch, d_scratch);
    cudaFuncSetAttribute(gemm_c, cudaFuncAttributeMaxDynamicSharedMemorySize, 90112);

    // Resolve input ordering (dict order vs reference-signature order)
    int GX, SX, PT, GEI, GB, SEI, SB, GW, SW, LW;
    if (n_in >= 4 && in_sizes[3] == 2 * EG) {
        GX = 0; SX = 1; PT = 2; GEI = 3; GB = 4; SEI = 5; SB = 6;
        GW = 7; SW = 16; LW = 25;
    } else {
        GX = 0; SX = 1; PT = 2; GW = 3; SW = 12; LW = 21;
        GEI = 27; GB = 28; SEI = 29; SB = 30;
    }

    const float* x0g = (const float*)d_in[GX];
    const float* x0s = (const float*)d_in[SX];
    const int* eig = (const int*)d_in[GEI];
    const int* eis = (const int*)d_in[SEI];
    const int* bag = (const int*)d_in[GB];
    const int* bas = (const int*)d_in[SB];

    float* aggg = scratch + AGG_G;  float* aggs = scratch + AGG_S;
    float* x1g  = scratch + X1_G;   float* x1s  = scratch + X1_S;
    float* x2g  = scratch + X2_G;   float* x2s  = scratch + X2_S;
    float* x3g  = scratch + X3_G;   float* x3s  = scratch + X3_S;
    float* wtg  = scratch + WT_G;   float* wts  = scratch + WT_S;
    float* b3g  = scratch + B_G;    float* b3s  = scratch + B_S;
    float* pool = scratch + POOL;
    float* cnt  = scratch + CNTO;
    int* degg = (int*)(scratch + DEG_G);   int* degs = (int*)(scratch + DEG_S);
    int* ptrg = (int*)(scratch + PTR_G);   int* ptrs = (int*)(scratch + PTR_S);
    int* filg = (int*)(scratch + FILL_G);  int* fils = (int*)(scratch + FILL_S);
    int* ssg  = (int*)(scratch + SS_G);    int* sss  = (int*)(scratch + SS_S);

    int b0 = (NG + 127) / 128, b1 = (NS + 127) / 128;

    // zero pooled sums + counts, and degree arrays
    zero_k<<<(772 + 255) / 256, 256>>>((float4*)pool, 772);
    zero_k<<<(15001 + 255) / 256, 256>>>((float4*)(scratch + DEG_G), 15001);

    // ---- build CSR (once; shared by all three layers) ----
    {
        int tot = EG + ES;
        hist_c<<<(tot + 255) / 256, 256>>>(eig, EG, degg, eis, ES, degs);
        scan2<<<2, 1024>>>(degg, ptrg, filg, NG, degs, ptrs, fils, NS);
        fill_c<<<(tot + 255) / 256, 256>>>(eig, EG, filg, ssg, eis, ES, fils, sss);
    }

    // ---- layer 1: c=64 -> o=128
    {
        int c = 64, o = 128, K = 128;
        int tot = (NG + NS) * 16;
        gather_c<<<(tot + 255) / 256, 256>>>(x0g, ptrg, ssg, aggg, NG,
                                             x0s, ptrs, sss, aggs, NS, c, 4);
        fuse_wc<<<dim3((2 * c * o + 255) / 256, 2), 256>>>(
            (const float*)d_in[GW + 0], (const float*)d_in[GW + 1],
            (const float*)d_in[SW + 0], (const float*)d_in[SW + 1], wtg, wts, c, o);
        size_t smem = (size_t)(64 * (K + 4) + 2 * 128 * 20) * 4;
        gemm_c<<<dim3(o / 64, b0 + b1), 256, smem>>>(
            aggg, x0g, wtg, (const float*)d_in[GW + 2], x1g, NG,
            aggs, x0s, wts, (const float*)d_in[SW + 2], x1s, NS,
            b0, c, K, o, 1);
    }
    // ---- layer 2: c=128 -> o=256
    {
        int c = 128, o = 256, K = 256;
        int tot = (NG + NS) * 32;
        gather_c<<<(tot + 255) / 256, 256>>>(x1g, ptrg, ssg, aggg, NG,
                                             x1s, ptrs, sss, aggs, NS, c, 5);
        fuse_wc<<<dim3((2 * c * o + 255) / 256, 2), 256>>>(
            (const float*)d_in[GW + 3], (const float*)d_in[GW + 4],
            (const float*)d_in[SW + 3], (const float*)d_in[SW + 4], wtg, wts, c, o);
        size_t smem = (size_t)(64 * (K + 4) + 2 * 128 * 20) * 4;
        gemm_c<<<dim3(o / 64, b0 + b1), 256, smem>>>(
            aggg, x1g, wtg, (const float*)d_in[GW + 5], x2g, NG,
            aggs, x1s, wts, (const float*)d_in[SW + 5], x2s, NS,
            b0, c, K, o, 1);
    }
    // ---- layer 3: GEMM first (linearity swap), then width-192 CSR gather, then pool
    {
        fuse_w3c<<<dim3((256 * 384 + 255) / 256, 2), 256>>>(
            (const float*)d_in[GW + 6], (const float*)d_in[GW + 7], (const float*)d_in[GW + 8],
            (const float*)d_in[SW + 6], (const float*)d_in[SW + 7], (const float*)d_in[SW + 8],
            wtg, b3g, wts, b3s);
        size_t smem = (size_t)(64 * (256 + 4) + 2 * 128 * 20) * 4;
        gemm_c<<<dim3(384 / 64, b0 + b1), 256, smem>>>(
            x2g, x2g, wtg, b3g, x3g, NG,
            x2s, x2s, wts, b3s, x3s, NS,
            b0, 256, 256, 384, 0);
        int tot = (NG + NS) * 48;
        gather3_c<<<(tot + 255) / 256, 256>>>(ptrg, ssg, x3g, NG, ptrs, sss, x3s, NS);
        int pb0 = (NG + 255) / 256, pb1 = (NS + 255) / 256;
        pool_c<<<pb0 + pb1, 192>>>(x3g, bag, pool, cnt, NG, pb0,
                                   x3s, bas, pool + 1536, cnt + 8, NS);
    }

    mlp_k<<<1, 640>>>((const float*)d_in[PT],
                      (const float*)d_in[LW + 0], (const float*)d_in[LW + 1],
                      (const float*)d_in[LW + 2], (const float*)d_in[LW + 3],
                      (const float*)d_in[LW + 4], (const float*)d_in[LW + 5],
                      pool, cnt, (float*)d_out);
}

// round 10
// speedup vs baseline: 4.1580x; 1.1497x over previous
#include <cuda_runtime.h>
#include <math.h>
#include <stdint.h>

#define NG 50000
#define NS 10000
#define EG 800000
#define ES 160000

// ---- scratch layout (single __device__ array, no allocations) ----
static const size_t AGG_G = 0;          // 50000*128 max
static const size_t AGG_S = 6400000;
static const size_t X1_G  = 7680000;    // 50000*128
static const size_t X1_S  = 14080000;
static const size_t X2_G  = 15360000;   // 50000*256
static const size_t X2_S  = 28160000;
static const size_t X3_G  = 30720000;   // 50000*384
static const size_t X3_S  = 49920000;
static const size_t POOL  = 53960800;   // 2*8*192
static const size_t CNTO  = 53963872;   // 16
// ---- CSR structures (ints stored in float scratch) ----
static const size_t DEG_G  = 53963904;  // 50001
static const size_t DEG_S  = 54013905;  // 10001 (contiguous with DEG_G for one zero pass)
static const size_t PTR_G  = 54023906;  // 50001
static const size_t PTR_S  = 54073907;  // 10001
static const size_t FILL_G = 54083908;  // 50000
static const size_t FILL_S = 54133908;  // 10000
static const size_t SS_G   = 54143908;  // 800000
static const size_t SS_S   = 54943908;  // 160000
static const size_t BS_G   = 55103908;  // 197 block sums (+total)
static const size_t BS_S   = 55104108;  // 41
__device__ float d_scratch[55104512];

__device__ __forceinline__ uint32_t f2tf32(float f) {
    uint32_t u;
    asm("cvt.rna.tf32.f32 %0, %1;" : "=r"(u) : "f"(f));
    return u;
}
__device__ __forceinline__ void ldsm_x4(uint32_t& r0, uint32_t& r1, uint32_t& r2, uint32_t& r3, uint32_t addr) {
    asm volatile("ldmatrix.sync.aligned.m8n8.x4.shared.b16 {%0,%1,%2,%3}, [%4];"
                 : "=r"(r0), "=r"(r1), "=r"(r2), "=r"(r3) : "r"(addr));
}
__device__ __forceinline__ void ldsm_x2(uint32_t& r0, uint32_t& r1, uint32_t addr) {
    asm volatile("ldmatrix.sync.aligned.m8n8.x2.shared.b16 {%0,%1}, [%2];"
                 : "=r"(r0), "=r"(r1) : "r"(addr));
}

// ---------------- zero ----------------
__global__ void zero_k(float4* p, int n4) {
    int i = blockIdx.x * blockDim.x + threadIdx.x;
    if (i < n4) p[i] = make_float4(0.f, 0.f, 0.f, 0.f);
}

// ---------------- CSR build: histogram, 3-phase scan, fill ----------------
__global__ void hist_c(const int* __restrict__ ei0, int E0, int* __restrict__ deg0,
                       const int* __restrict__ ei1, int E1, int* __restrict__ deg1) {
    int i = blockIdx.x * 256 + threadIdx.x;
    if (i < E0) atomicAdd(&deg0[ei0[E0 + i]], 1);
    else {
        int j = i - E0;
        if (j < E1) atomicAdd(&deg1[ei1[E1 + j]], 1);
    }
}

// phase 1: per-block exclusive scan of 256 elems; block total -> bs[b]
__global__ void scan_blk(const int* __restrict__ dga, int* __restrict__ pta,
                         int* __restrict__ bsa, int Na, int nba,
                         const int* __restrict__ dgb, int* __restrict__ ptb,
                         int* __restrict__ bsb, int Nb) {
    const int* deg; int* ptr; int* bs; int N, b;
    if ((int)blockIdx.x < nba) { deg = dga; ptr = pta; bs = bsa; N = Na; b = blockIdx.x; }
    else                        { deg = dgb; ptr = ptb; bs = bsb; N = Nb; b = blockIdx.x - nba; }
    __shared__ int s[256];
    int t = threadIdx.x, i = b * 256 + t;
    int v = (i < N) ? deg[i] : 0;
    s[t] = v;
    __syncthreads();
    #pragma unroll
    for (int off = 1; off < 256; off <<= 1) {
        int u = (t >= off) ? s[t - off] : 0;
        __syncthreads();
        s[t] += u;
        __syncthreads();
    }
    if (i < N) ptr[i] = s[t] - v;
    if (t == 255) bs[b] = s[255];
}

// phase 2: exclusive scan of block sums (n <= 256); total stored at bs[n]
__global__ void scan_top(int* __restrict__ bsa, int na, int* __restrict__ bsb, int nb) {
    int* bs; int n;
    if (blockIdx.x == 0) { bs = bsa; n = na; } else { bs = bsb; n = nb; }
    __shared__ int s[256];
    int t = threadIdx.x;
    int v = (t < n) ? bs[t] : 0;
    s[t] = v;
    __syncthreads();
    #pragma unroll
    for (int off = 1; off < 256; off <<= 1) {
        int u = (t >= off) ? s[t - off] : 0;
        __syncthreads();
        s[t] += u;
        __syncthreads();
    }
    if (t < n) bs[t] = s[t] - v;
    if (t == 255) bs[n] = s[255];
}

// phase 3: add block offsets; init fill; write ptr[N]
__global__ void scan_add(int* __restrict__ pta, int* __restrict__ fla,
                         const int* __restrict__ bsa, int Na, int nba,
                         int* __restrict__ ptb, int* __restrict__ flb,
                         const int* __restrict__ bsb, int Nb, int nbb) {
    int idx = blockIdx.x * 256 + threadIdx.x;
    int* ptr; int* fl; const int* bs; int N, i, nb;
    if (idx <= Na) { ptr = pta; fl = fla; bs = bsa; N = Na; i = idx; nb = nba; }
    else {
        i = idx - Na - 1;
        if (i > Nb) return;
        ptr = ptb; fl = flb; bs = bsb; N = Nb; nb = nbb;
    }
    if (i < N) {
        int p = ptr[i] + bs[i >> 8];
        ptr[i] = p;
        fl[i] = p;
    } else {
        ptr[N] = bs[nb];
    }
}

__global__ void fill_c(const int* __restrict__ ei0, int E0, int* __restrict__ fill0, int* __restrict__ ss0,
                       const int* __restrict__ ei1, int E1, int* __restrict__ fill1, int* __restrict__ ss1) {
    int i = blockIdx.x * 256 + threadIdx.x;
    if (i < E0) {
        int dst = ei0[E0 + i];
        int p = atomicAdd(&fill0[dst], 1);
        ss0[p] = ei0[i];
    } else {
        int j = i - E0;
        if (j >= E1) return;
        int dst = ei1[E1 + j];
        int p = atomicAdd(&fill1[dst], 1);
        ss1[p] = ei1[j];
    }
}

// ---------------- CSR gather: agg[n] = sum over incoming edges of x[src] ----------------
__global__ void gather_c(const float* __restrict__ x0, const int* __restrict__ ptr0,
                         const int* __restrict__ ss0, float* __restrict__ agg0, int N0,
                         const float* __restrict__ x1, const int* __restrict__ ptr1,
                         const int* __restrict__ ss1, float* __restrict__ agg1, int N1,
                         int c, int shift) {
    int idx = blockIdx.x * 256 + threadIdx.x;
    const float* x; const int* ptr; const int* ss; float* agg; int i;
    int t0 = N0 << shift;
    if (idx < t0) { x = x0; ptr = ptr0; ss = ss0; agg = agg0; i = idx; }
    else {
        i = idx - t0;
        if (i >= (N1 << shift)) return;
        x = x1; ptr = ptr1; ss = ss1; agg = agg1;
    }
    int n = i >> shift;
    int q = (i & ((1 << shift) - 1)) << 2;
    int e0 = ptr[n], e1 = ptr[n + 1];
    float4 acc = make_float4(0.f, 0.f, 0.f, 0.f);
    for (int e = e0; e < e1; e++) {
        int s = ss[e];
        float4 v = *(const float4*)(x + (size_t)s * c + q);
        acc.x += v.x; acc.y += v.y; acc.z += v.z; acc.w += v.w;
    }
    *(float4*)(agg + (size_t)n * c + q) = acc;
}

// layer-3 gather: x3[n,192+q] += sum x3[src,q]  (rows 384 wide; in-place, disjoint col ranges)
__global__ void gather3_c(const int* __restrict__ ptr0, const int* __restrict__ ss0,
                          float* __restrict__ x30, int N0,
                          const int* __restrict__ ptr1, const int* __restrict__ ss1,
                          float* __restrict__ x31, int N1) {
    int idx = blockIdx.x * 256 + threadIdx.x;
    const int* ptr; const int* ss; float* x3; int i;
    int t0 = N0 * 48;
    if (idx < t0) { ptr = ptr0; ss = ss0; x3 = x30; i = idx; }
    else {
        i = idx - t0;
        if (i >= N1 * 48) return;
        ptr = ptr1; ss = ss1; x3 = x31;
    }
    int n = i / 48;
    int q = (i - n * 48) << 2;
    int e0 = ptr[n], e1 = ptr[n + 1];
    float4 acc = *(const float4*)(x3 + (size_t)n * 384 + 192 + q);
    for (int e = e0; e < e1; e++) {
        int s = ss[e];
        float4 v = *(const float4*)(x3 + (size_t)s * 384 + q);
        acc.x += v.x; acc.y += v.y; acc.z += v.z; acc.w += v.w;
    }
    *(float4*)(x3 + (size_t)n * 384 + 192 + q) = acc;
}

// ---------------- tf32 GEMM: weights loaded directly (no staging), resident n-major B,
// reg-double-buffered A, ldmatrix fragment loads.
// mode 0: out = ELU([A1|A2(k>=c)] @ [Wr|Wn]^T + bias), B row n = [Wr[n][:], Wn[n][:]]
// mode 1: layer 3 — B row n = (n<192 ? W3r[n][:] : W3n[n-192][:]), bias = (n<192 ? 0 : B3[n-192])
__global__ void gemm_c(const float* __restrict__ A1g, const float* __restrict__ A2g,
                       const float* __restrict__ Wrg, const float* __restrict__ Wng,
                       const float* __restrict__ bgg, float* __restrict__ outg, int N0,
                       const float* __restrict__ A1s, const float* __restrict__ A2s,
                       const float* __restrict__ Wrs, const float* __restrict__ Wns,
                       const float* __restrict__ bss, float* __restrict__ outs, int N1,
                       int blocks0, int c, int K, int kq2, int o, int mode) {
    extern __shared__ uint32_t sm[];
    int bs = K + 4;
    uint32_t* Bp = sm;                 // [64][K+4]  (n-major, tf32)
    uint32_t* Ap = sm + 64 * bs;       // [2][128][20]

    const float *A1, *A2, *Wr, *Wn, *bias; float* out; int Nrows, m0;
    int by = blockIdx.y;
    if (by < blocks0) { A1 = A1g; A2 = A2g; Wr = Wrg; Wn = Wng; bias = bgg; out = outg; Nrows = N0; m0 = by * 128; }
    else              { A1 = A1s; A2 = A2s; Wr = Wrs; Wn = Wns; bias = bss; out = outs; Nrows = N1; m0 = (by - blocks0) * 128; }
    int n0 = blockIdx.x * 64;
    int tid = threadIdx.x, warp = tid >> 5, lane = tid & 31;
    int wm = warp >> 2, wn = warp & 3, lr = lane >> 2, lc = lane & 3;

    // resident B straight from weights: coalesced k-major float4 reads
    int kq = 1 << kq2;
    for (int i = tid; i < 64 * kq; i += 256) {
        int n = i >> kq2, k = (i & (kq - 1)) << 2;
        int ng = n0 + n;
        const float* src;
        if (mode == 0) src = (k < c) ? (Wr + (size_t)ng * c + k) : (Wn + (size_t)ng * c + (k - c));
        else           src = (ng < 192) ? (Wr + (size_t)ng * 256 + k) : (Wn + (size_t)(ng - 192) * 256 + k);
        float4 v = *(const float4*)src;
        Bp[n * bs + k + 0] = f2tf32(v.x);
        Bp[n * bs + k + 1] = f2tf32(v.y);
        Bp[n * bs + k + 2] = f2tf32(v.z);
        Bp[n * bs + k + 3] = f2tf32(v.w);
    }

    uint32_t b_base = (uint32_t)__cvta_generic_to_shared(Bp);
    uint32_t a_base0 = (uint32_t)__cvta_generic_to_shared(Ap);
    uint32_t a_base1 = a_base0 + 128 * 20 * 4;
    int arow = lane & 15, acolo = (lane >> 4) << 2;       // ldmatrix.x4 lane addressing
    int brow = lane & 7,  bcolo = ((lane >> 3) & 1) << 2; // ldmatrix.x2 lane addressing

    float acc[4][2][4] = {};
    int am = tid >> 2, akq = (tid & 3) << 2;
    int gm0 = m0 + am, gm1 = m0 + am + 64;
    float4 st0, st1;
    st0 = (gm0 < Nrows) ? *(const float4*)(A1 + (size_t)gm0 * c + akq) : make_float4(0.f, 0.f, 0.f, 0.f);
    st1 = (gm1 < Nrows) ? *(const float4*)(A1 + (size_t)gm1 * c + akq) : make_float4(0.f, 0.f, 0.f, 0.f);

    int iters = K >> 4;
    for (int it = 0; it < iters; it++) {
        uint32_t* Ab = Ap + (it & 1) * (128 * 20);
        uint32_t a_base = (it & 1) ? a_base1 : a_base0;
        *(uint4*)&Ab[am * 20 + akq]        = make_uint4(f2tf32(st0.x), f2tf32(st0.y), f2tf32(st0.z), f2tf32(st0.w));
        *(uint4*)&Ab[(am + 64) * 20 + akq] = make_uint4(f2tf32(st1.x), f2tf32(st1.y), f2tf32(st1.z), f2tf32(st1.w));
        __syncthreads();
        if (it + 1 < iters) {
            int k0 = (it + 1) << 4;
            const float* A = (k0 < c) ? A1 : A2;
            int col0 = (k0 < c) ? k0 : (k0 - c);
            st0 = (gm0 < Nrows) ? *(const float4*)(A + (size_t)gm0 * c + col0 + akq) : make_float4(0.f, 0.f, 0.f, 0.f);
            st1 = (gm1 < Nrows) ? *(const float4*)(A + (size_t)gm1 * c + col0 + akq) : make_float4(0.f, 0.f, 0.f, 0.f);
        }
        int kbase = it << 4;
        #pragma unroll
        for (int ks = 0; ks < 2; ks++) {
            int kq_ = ks << 3;
            uint32_t af[4][4];
            #pragma unroll
            for (int mt = 0; mt < 4; mt++) {
                int mb = wm * 64 + mt * 16;
                uint32_t addr = a_base + (uint32_t)(((mb + arow) * 20 + kq_ + acolo) << 2);
                ldsm_x4(af[mt][0], af[mt][1], af[mt][2], af[mt][3], addr);
            }
            uint32_t bf[2][2];
            #pragma unroll
            for (int nt = 0; nt < 2; nt++) {
                int nb = wn * 16 + nt * 8;
                uint32_t addr = b_base + (uint32_t)(((nb + brow) * bs + kbase + kq_ + bcolo) << 2);
                ldsm_x2(bf[nt][0], bf[nt][1], addr);
            }
            #pragma unroll
            for (int nt = 0; nt < 2; nt++) {
                #pragma unroll
                for (int mt = 0; mt < 4; mt++) {
                    asm volatile(
                        "mma.sync.aligned.m16n8k8.row.col.f32.tf32.tf32.f32 "
                        "{%0,%1,%2,%3}, {%4,%5,%6,%7}, {%8,%9}, {%0,%1,%2,%3};"
                        : "+f"(acc[mt][nt][0]), "+f"(acc[mt][nt][1]),
                          "+f"(acc[mt][nt][2]), "+f"(acc[mt][nt][3])
                        : "r"(af[mt][0]), "r"(af[mt][1]), "r"(af[mt][2]), "r"(af[mt][3]),
                          "r"(bf[nt][0]), "r"(bf[nt][1]));
                }
            }
        }
    }

    int mrow0 = m0 + wm * 64;
    #pragma unroll
    for (int mt = 0; mt < 4; mt++) {
        #pragma unroll
        for (int half = 0; half < 2; half++) {
            int m = mrow0 + mt * 16 + lr + half * 8;
            if (m >= Nrows) continue;
            #pragma unroll
            for (int nt = 0; nt < 2; nt++) {
                int n = n0 + wn * 16 + nt * 8 + 2 * lc;
                float b0v, b1v;
                if (mode == 0) { b0v = bias[n]; b1v = bias[n + 1]; }
                else { b0v = (n >= 192) ? bias[n - 192] : 0.f; b1v = (n + 1 >= 192) ? bias[n + 1 - 192] : 0.f; }
                float v0 = acc[mt][nt][half * 2 + 0] + b0v;
                float v1 = acc[mt][nt][half * 2 + 1] + b1v;
                if (mode == 0) {
                    v0 = (v0 > 0.f) ? v0 : expm1f(v0);
                    v1 = (v1 > 0.f) ? v1 : expm1f(v1);
                }
                *(float2*)(out + (size_t)m * o + n) = make_float2(v0, v1);
            }
        }
    }
}

// ---------------- pooling (both branches, count fused; batch sorted) ----------------
__global__ void pool_c(const float* __restrict__ x3a, const int* __restrict__ ba,
                       float* __restrict__ pa, float* __restrict__ ca, int N0, int blocks0,
                       const float* __restrict__ x3b, const int* __restrict__ bb,
                       float* __restrict__ pb, float* __restrict__ cb, int N1) {
    const float* x3; const int* batch; float* pool; float* cnt; int N, blk;
    if ((int)blockIdx.x < blocks0) { x3 = x3a; batch = ba; pool = pa; cnt = ca; N = N0; blk = blockIdx.x; }
    else { x3 = x3b; batch = bb; pool = pb; cnt = cb; N = N1; blk = blockIdx.x - blocks0; }
    int t = threadIdx.x;   // 0..191
    int r0 = blk * 256;
    int rend = r0 + 256; if (rend > N) rend = N;
    if (r0 >= N) return;
    int cur = batch[r0];
    float acc = 0.f, cacc = 0.f;
    for (int i = r0; i < rend; i++) {
        int b = batch[i];
        if (b != cur) {
            atomicAdd(&pool[cur * 192 + t], acc);
            if (t == 0) atomicAdd(&cnt[cur], cacc);
            acc = 0.f; cacc = 0.f; cur = b;
        }
        float v = x3[(size_t)i * 384 + 192 + t];
        v = (v > 0.f) ? v : expm1f(v);
        acc += v; cacc += 1.f;
    }
    atomicAdd(&pool[cur * 192 + t], acc);
    if (t == 0) atomicAdd(&cnt[cur], cacc);
}

// ---------------- final MLP (single block): mean-div + 448->600->256->64 ----------------
__global__ void mlp_k(const float* __restrict__ point,
                      const float* __restrict__ l1W, const float* __restrict__ l1b,
                      const float* __restrict__ l2W, const float* __restrict__ l2b,
                      const float* __restrict__ l3W, const float* __restrict__ l3b,
                      const float* __restrict__ pool, const float* __restrict__ cnt,
                      float* __restrict__ out) {
    __shared__ float inT[448][8];
    __shared__ float h1[600][8];
    __shared__ float h2[256][8];
    int t = threadIdx.x;

    for (int idx = t; idx < 448 * 8; idx += blockDim.x) {
        int r = idx & 7, f = idx >> 3;
        float v;
        if (f < 192)       v = pool[r * 192 + f] / fmaxf(cnt[r], 1.f);
        else if (f < 384)  v = pool[1536 + r * 192 + (f - 192)] / fmaxf(cnt[8 + r], 1.f);
        else               v = point[r * 64 + (f - 384)];
        inT[f][r] = v;
    }
    __syncthreads();

    if (t < 600) {
        float acc[8];
        float b = l1b[t];
        #pragma unroll
        for (int r = 0; r < 8; r++) acc[r] = b;
        for (int f = 0; f < 448; f++) {
            float w = l1W[t * 448 + f];
            float4 p0 = *(const float4*)&inT[f][0];
            float4 p1 = *(const float4*)&inT[f][4];
            acc[0] += w * p0.x; acc[1] += w * p0.y; acc[2] += w * p0.z; acc[3] += w * p0.w;
            acc[4] += w * p1.x; acc[5] += w * p1.y; acc[6] += w * p1.z; acc[7] += w * p1.w;
        }
        #pragma unroll
        for (int r = 0; r < 8; r++) h1[t][r] = fmaxf(acc[r], 0.f);
    }
    __syncthreads();

    if (t < 256) {
        float acc[8];
        float b = l2b[t];
        #pragma unroll
        for (int r = 0; r < 8; r++) acc[r] = b;
        for (int f = 0; f < 600; f++) {
            float w = l2W[t * 600 + f];
            float4 p0 = *(const float4*)&h1[f][0];
            float4 p1 = *(const float4*)&h1[f][4];
            acc[0] += w * p0.x; acc[1] += w * p0.y; acc[2] += w * p0.z; acc[3] += w * p0.w;
            acc[4] += w * p1.x; acc[5] += w * p1.y; acc[6] += w * p1.z; acc[7] += w * p1.w;
        }
        #pragma unroll
        for (int r = 0; r < 8; r++) h2[t][r] = fmaxf(acc[r], 0.f);
    }
    __syncthreads();

    if (t < 64) {
        float acc[8];
        float b = l3b[t];
        #pragma unroll
        for (int r = 0; r < 8; r++) acc[r] = b;
        for (int f = 0; f < 256; f++) {
            float w = l3W[t * 256 + f];
            float4 p0 = *(const float4*)&h2[f][0];
            float4 p1 = *(const float4*)&h2[f][4];
            acc[0] += w * p0.x; acc[1] += w * p0.y; acc[2] += w * p0.z; acc[3] += w * p0.w;
            acc[4] += w * p1.x; acc[5] += w * p1.y; acc[6] += w * p1.z; acc[7] += w * p1.w;
        }
        #pragma unroll
        for (int r = 0; r < 8; r++) out[r * 64 + t] = acc[r];
    }
}

extern "C" void kernel_launch(void* const* d_in, const int* in_sizes, int n_in,
                              void* d_out, int out_size) {
    float* scratch = nullptr;
    cudaGetSymbolAddress((void**)&scratch, d_scratch);
    cudaFuncSetAttribute(gemm_c, cudaFuncAttributeMaxDynamicSharedMemorySize, 90112);

    // Resolve input ordering (dict order vs reference-signature order)
    int GX, SX, PT, GEI, GB, SEI, SB, GW, SW, LW;
    if (n_in >= 4 && in_sizes[3] == 2 * EG) {
        GX = 0; SX = 1; PT = 2; GEI = 3; GB = 4; SEI = 5; SB = 6;
        GW = 7; SW = 16; LW = 25;
    } else {
        GX = 0; SX = 1; PT = 2; GW = 3; SW = 12; LW = 21;
        GEI = 27; GB = 28; SEI = 29; SB = 30;
    }

    const float* x0g = (const float*)d_in[GX];
    const float* x0s = (const float*)d_in[SX];
    const int* eig = (const int*)d_in[GEI];
    const int* eis = (const int*)d_in[SEI];
    const int* bag = (const int*)d_in[GB];
    const int* bas = (const int*)d_in[SB];

    float* aggg = scratch + AGG_G;  float* aggs = scratch + AGG_S;
    float* x1g  = scratch + X1_G;   float* x1s  = scratch + X1_S;
    float* x2g  = scratch + X2_G;   float* x2s  = scratch + X2_S;
    float* x3g  = scratch + X3_G;   float* x3s  = scratch + X3_S;
    float* pool = scratch + POOL;
    float* cnt  = scratch + CNTO;
    int* degg = (int*)(scratch + DEG_G);   int* degs = (int*)(scratch + DEG_S);
    int* ptrg = (int*)(scratch + PTR_G);   int* ptrs = (int*)(scratch + PTR_S);
    int* filg = (int*)(scratch + FILL_G);  int* fils = (int*)(scratch + FILL_S);
    int* ssg  = (int*)(scratch + SS_G);    int* sss  = (int*)(scratch + SS_S);
    int* bsg  = (int*)(scratch + BS_G);    int* bss  = (int*)(scratch + BS_S);

    int b0 = (NG + 127) / 128, b1 = (NS + 127) / 128;
    int nbg = (NG + 255) / 256, nbs = (NS + 255) / 256;

    // zero pooled sums + counts, and degree arrays
    zero_k<<<(772 + 255) / 256, 256>>>((float4*)pool, 772);
    zero_k<<<(15001 + 255) / 256, 256>>>((float4*)(scratch + DEG_G), 15001);

    // ---- build CSR (once; shared by all three layers) ----
    {
        int tot = EG + ES;
        hist_c<<<(tot + 255) / 256, 256>>>(eig, EG, degg, eis, ES, degs);
        scan_blk<<<nbg + nbs, 256>>>(degg, ptrg, bsg, NG, nbg, degs, ptrs, bss, NS);
        scan_top<<<2, 256>>>(bsg, nbg, bss, nbs);
        scan_add<<<(NG + NS + 2 + 255) / 256, 256>>>(ptrg, filg, bsg, NG, nbg,
                                                     ptrs, fils, bss, NS, nbs);
        fill_c<<<(tot + 255) / 256, 256>>>(eig, EG, filg, ssg, eis, ES, fils, sss);
    }

    // ---- layer 1: c=64 -> o=128, K=128 (kq2=5)
    {
        int c = 64, o = 128, K = 128;
        int tot = (NG + NS) * 16;
        gather_c<<<(tot + 255) / 256, 256>>>(x0g, ptrg, ssg, aggg, NG,
                                             x0s, ptrs, sss, aggs, NS, c, 4);
        size_t smem = (size_t)(64 * (K + 4) + 2 * 128 * 20) * 4;
        gemm_c<<<dim3(o / 64, b0 + b1), 256, smem>>>(
            aggg, x0g, (const float*)d_in[GW + 0], (const float*)d_in[GW + 1],
            (const float*)d_in[GW + 2], x1g, NG,
            aggs, x0s, (const float*)d_in[SW + 0], (const float*)d_in[SW + 1],
            (const float*)d_in[SW + 2], x1s, NS,
            b0, c, K, 5, o, 0);
    }
    // ---- layer 2: c=128 -> o=256, K=256 (kq2=6)
    {
        int c = 128, o = 256, K = 256;
        int tot = (NG + NS) * 32;
        gather_c<<<(tot + 255) / 256, 256>>>(x1g, ptrg, ssg, aggg, NG,
                                             x1s, ptrs, sss, aggs, NS, c, 5);
        size_t smem = (size_t)(64 * (K + 4) + 2 * 128 * 20) * 4;
        gemm_c<<<dim3(o / 64, b0 + b1), 256, smem>>>(
            aggg, x1g, (const float*)d_in[GW + 3], (const float*)d_in[GW + 4],
            (const float*)d_in[GW + 5], x2g, NG,
            aggs, x1s, (const float*)d_in[SW + 3], (const float*)d_in[SW + 4],
            (const float*)d_in[SW + 5], x2s, NS,
            b0, c, K, 6, o, 0);
    }
    // ---- layer 3: GEMM first (linearity swap), then width-192 CSR gather, then pool
    {
        size_t smem = (size_t)(64 * (256 + 4) + 2 * 128 * 20) * 4;
        gemm_c<<<dim3(384 / 64, b0 + b1), 256, smem>>>(
            x2g, x2g, (const float*)d_in[GW + 6], (const float*)d_in[GW + 7],
            (const float*)d_in[GW + 8], x3g, NG,
            x2s, x2s, (const float*)d_in[SW + 6], (const float*)d_in[SW + 7],
            (const float*)d_in[SW + 8], x3s, NS,
            b0, 256, 256, 6, 384, 1);
        int tot = (NG + NS) * 48;
        gather3_c<<<(tot + 255) / 256, 256>>>(ptrg, ssg, x3g, NG, ptrs, sss, x3s, NS);
        int pb0 = (NG + 255) / 256, pb1 = (NS + 255) / 256;
        pool_c<<<pb0 + pb1, 192>>>(x3g, bag, pool, cnt, NG, pb0,
                                   x3s, bas, pool + 1536, cnt + 8, NS);
    }

    mlp_k<<<1, 640>>>((const float*)d_in[PT],
                      (const float*)d_in[LW + 0], (const float*)d_in[LW + 1],
                      (const float*)d_in[LW + 2], (const float*)d_in[LW + 3],
                      (const float*)d_in[LW + 4], (const float*)d_in[LW + 5],
                      pool, cnt, (float*)d_out);
}

// round 11
// speedup vs baseline: 4.1931x; 1.0084x over previous
#include <cuda_runtime.h>
#include <math.h>
#include <stdint.h>

#define NG 50000
#define NS 10000
#define EG 800000
#define ES 160000

// ---- scratch layout (single __device__ array, no allocations) ----
static const size_t AGG_G = 0;          // 50000*128 max
static const size_t AGG_S = 6400000;
static const size_t X1_G  = 7680000;    // 50000*128
static const size_t X1_S  = 14080000;
static const size_t X2_G  = 15360000;   // 50000*256
static const size_t X2_S  = 28160000;
static const size_t X3_G  = 30720000;   // 50000*384
static const size_t X3_S  = 49920000;
static const size_t POOL  = 53960800;   // 2*8*192
static const size_t CNTO  = 53963872;   // 16
// ---- CSR structures (ints stored in float scratch) ----
static const size_t DEG_G  = 53963904;  // 50001
static const size_t DEG_S  = 54013905;  // 10001 (contiguous with DEG_G for one zero pass)
static const size_t PTR_G  = 54023906;  // 50001
static const size_t PTR_S  = 54073907;  // 10001
static const size_t FILL_G = 54083908;  // 50000
static const size_t FILL_S = 54133908;  // 10000
static const size_t SS_G   = 54143908;  // 800000
static const size_t SS_S   = 54943908;  // 160000
static const size_t BS_G   = 55103908;  // 197 block sums (+total)
static const size_t BS_S   = 55104108;  // 41
__device__ float d_scratch[55104512];

__device__ __forceinline__ uint32_t f2tf32(float f) {
    uint32_t u;
    asm("cvt.rna.tf32.f32 %0, %1;" : "=r"(u) : "f"(f));
    return u;
}
__device__ __forceinline__ void ldsm_x4(uint32_t& r0, uint32_t& r1, uint32_t& r2, uint32_t& r3, uint32_t addr) {
    asm volatile("ldmatrix.sync.aligned.m8n8.x4.shared.b16 {%0,%1,%2,%3}, [%4];"
                 : "=r"(r0), "=r"(r1), "=r"(r2), "=r"(r3) : "r"(addr));
}

// ---------------- zero ----------------
__global__ void zero_k(float4* p, int n4) {
    int i = blockIdx.x * blockDim.x + threadIdx.x;
    if (i < n4) p[i] = make_float4(0.f, 0.f, 0.f, 0.f);
}

// ---------------- CSR build: histogram, 3-phase scan, fill ----------------
__global__ void hist_c(const int* __restrict__ ei0, int E0, int* __restrict__ deg0,
                       const int* __restrict__ ei1, int E1, int* __restrict__ deg1) {
    int i = blockIdx.x * 256 + threadIdx.x;
    if (i < E0) atomicAdd(&deg0[ei0[E0 + i]], 1);
    else {
        int j = i - E0;
        if (j < E1) atomicAdd(&deg1[ei1[E1 + j]], 1);
    }
}

__global__ void scan_blk(const int* __restrict__ dga, int* __restrict__ pta,
                         int* __restrict__ bsa, int Na, int nba,
                         const int* __restrict__ dgb, int* __restrict__ ptb,
                         int* __restrict__ bsb, int Nb) {
    const int* deg; int* ptr; int* bs; int N, b;
    if ((int)blockIdx.x < nba) { deg = dga; ptr = pta; bs = bsa; N = Na; b = blockIdx.x; }
    else                        { deg = dgb; ptr = ptb; bs = bsb; N = Nb; b = blockIdx.x - nba; }
    __shared__ int s[256];
    int t = threadIdx.x, i = b * 256 + t;
    int v = (i < N) ? deg[i] : 0;
    s[t] = v;
    __syncthreads();
    #pragma unroll
    for (int off = 1; off < 256; off <<= 1) {
        int u = (t >= off) ? s[t - off] : 0;
        __syncthreads();
        s[t] += u;
        __syncthreads();
    }
    if (i < N) ptr[i] = s[t] - v;
    if (t == 255) bs[b] = s[255];
}

__global__ void scan_top(int* __restrict__ bsa, int na, int* __restrict__ bsb, int nb) {
    int* bs; int n;
    if (blockIdx.x == 0) { bs = bsa; n = na; } else { bs = bsb; n = nb; }
    __shared__ int s[256];
    int t = threadIdx.x;
    int v = (t < n) ? bs[t] : 0;
    s[t] = v;
    __syncthreads();
    #pragma unroll
    for (int off = 1; off < 256; off <<= 1) {
        int u = (t >= off) ? s[t - off] : 0;
        __syncthreads();
        s[t] += u;
        __syncthreads();
    }
    if (t < n) bs[t] = s[t] - v;
    if (t == 255) bs[n] = s[255];
}

__global__ void scan_add(int* __restrict__ pta, int* __restrict__ fla,
                         const int* __restrict__ bsa, int Na, int nba,
                         int* __restrict__ ptb, int* __restrict__ flb,
                         const int* __restrict__ bsb, int Nb, int nbb) {
    int idx = blockIdx.x * 256 + threadIdx.x;
    int* ptr; int* fl; const int* bs; int N, i, nb;
    if (idx <= Na) { ptr = pta; fl = fla; bs = bsa; N = Na; i = idx; nb = nba; }
    else {
        i = idx - Na - 1;
        if (i > Nb) return;
        ptr = ptb; fl = flb; bs = bsb; N = Nb; nb = nbb;
    }
    if (i < N) {
        int p = ptr[i] + bs[i >> 8];
        ptr[i] = p;
        fl[i] = p;
    } else {
        ptr[N] = bs[nb];
    }
}

__global__ void fill_c(const int* __restrict__ ei0, int E0, int* __restrict__ fill0, int* __restrict__ ss0,
                       const int* __restrict__ ei1, int E1, int* __restrict__ fill1, int* __restrict__ ss1) {
    int i = blockIdx.x * 256 + threadIdx.x;
    if (i < E0) {
        int dst = ei0[E0 + i];
        int p = atomicAdd(&fill0[dst], 1);
        ss0[p] = ei0[i];
    } else {
        int j = i - E0;
        if (j >= E1) return;
        int dst = ei1[E1 + j];
        int p = atomicAdd(&fill1[dst], 1);
        ss1[p] = ei1[j];
    }
}

// ---------------- CSR gather (2-way unrolled, dual accumulators) ----------------
__global__ void gather_c(const float* __restrict__ x0, const int* __restrict__ ptr0,
                         const int* __restrict__ ss0, float* __restrict__ agg0, int N0,
                         const float* __restrict__ x1, const int* __restrict__ ptr1,
                         const int* __restrict__ ss1, float* __restrict__ agg1, int N1,
                         int c, int shift) {
    int idx = blockIdx.x * 256 + threadIdx.x;
    const float* x; const int* ptr; const int* ss; float* agg; int i;
    int t0 = N0 << shift;
    if (idx < t0) { x = x0; ptr = ptr0; ss = ss0; agg = agg0; i = idx; }
    else {
        i = idx - t0;
        if (i >= (N1 << shift)) return;
        x = x1; ptr = ptr1; ss = ss1; agg = agg1;
    }
    int n = i >> shift;
    int q = (i & ((1 << shift) - 1)) << 2;
    int e0 = ptr[n], e1 = ptr[n + 1];
    float4 a0 = make_float4(0.f, 0.f, 0.f, 0.f);
    float4 a1 = make_float4(0.f, 0.f, 0.f, 0.f);
    int e = e0;
    for (; e + 1 < e1; e += 2) {
        int s0 = __ldg(ss + e), s1 = __ldg(ss + e + 1);
        float4 v0 = __ldg((const float4*)(x + (size_t)s0 * c + q));
        float4 v1 = __ldg((const float4*)(x + (size_t)s1 * c + q));
        a0.x += v0.x; a0.y += v0.y; a0.z += v0.z; a0.w += v0.w;
        a1.x += v1.x; a1.y += v1.y; a1.z += v1.z; a1.w += v1.w;
    }
    if (e < e1) {
        int s0 = __ldg(ss + e);
        float4 v0 = __ldg((const float4*)(x + (size_t)s0 * c + q));
        a0.x += v0.x; a0.y += v0.y; a0.z += v0.z; a0.w += v0.w;
    }
    a0.x += a1.x; a0.y += a1.y; a0.z += a1.z; a0.w += a1.w;
    *(float4*)(agg + (size_t)n * c + q) = a0;
}

// layer-3 gather: x3[n,192+q] += sum x3[src,q]  (rows 384 wide; in-place, disjoint col ranges)
__global__ void gather3_c(const int* __restrict__ ptr0, const int* __restrict__ ss0,
                          float* __restrict__ x30, int N0,
                          const int* __restrict__ ptr1, const int* __restrict__ ss1,
                          float* __restrict__ x31, int N1) {
    int idx = blockIdx.x * 256 + threadIdx.x;
    const int* ptr; const int* ss; float* x3; int i;
    int t0 = N0 * 48;
    if (idx < t0) { ptr = ptr0; ss = ss0; x3 = x30; i = idx; }
    else {
        i = idx - t0;
        if (i >= N1 * 48) return;
        ptr = ptr1; ss = ss1; x3 = x31;
    }
    int n = i / 48;
    int q = (i - n * 48) << 2;
    int e0 = ptr[n], e1 = ptr[n + 1];
    float4 a0 = *(const float4*)(x3 + (size_t)n * 384 + 192 + q);
    float4 a1 = make_float4(0.f, 0.f, 0.f, 0.f);
    int e = e0;
    for (; e + 1 < e1; e += 2) {
        int s0 = __ldg(ss + e), s1 = __ldg(ss + e + 1);
        float4 v0 = __ldg((const float4*)(x3 + (size_t)s0 * 384 + q));
        float4 v1 = __ldg((const float4*)(x3 + (size_t)s1 * 384 + q));
        a0.x += v0.x; a0.y += v0.y; a0.z += v0.z; a0.w += v0.w;
        a1.x += v1.x; a1.y += v1.y; a1.z += v1.z; a1.w += v1.w;
    }
    if (e < e1) {
        int s0 = __ldg(ss + e);
        float4 v0 = __ldg((const float4*)(x3 + (size_t)s0 * 384 + q));
        a0.x += v0.x; a0.y += v0.y; a0.z += v0.z; a0.w += v0.w;
    }
    a0.x += a1.x; a0.y += a1.y; a0.z += a1.z; a0.w += a1.w;
    *(float4*)(x3 + (size_t)n * 384 + 192 + q) = a0;
}

// ---------------- tf32 GEMM: weights loaded directly, resident n-major B,
// reg-double-buffered A, ldmatrix fragment loads (B via single x4).
// mode 0: out = ELU([A1|A2(k>=c)] @ [Wr|Wn]^T + bias)
// mode 1: layer 3 — B row n = (n<192 ? W3r[n] : W3n[n-192]), bias = (n<192 ? 0 : B3[n-192])
__global__ void gemm_c(const float* __restrict__ A1g, const float* __restrict__ A2g,
                       const float* __restrict__ Wrg, const float* __restrict__ Wng,
                       const float* __restrict__ bgg, float* __restrict__ outg, int N0,
                       const float* __restrict__ A1s, const float* __restrict__ A2s,
                       const float* __restrict__ Wrs, const float* __restrict__ Wns,
                       const float* __restrict__ bss, float* __restrict__ outs, int N1,
                       int blocks0, int c, int K, int kq2, int o, int mode) {
    extern __shared__ uint32_t sm[];
    int bs = K + 4;
    uint32_t* Bp = sm;                 // [64][K+4]  (n-major, tf32)
    uint32_t* Ap = sm + 64 * bs;       // [2][128][20]

    const float *A1, *A2, *Wr, *Wn, *bias; float* out; int Nrows, m0;
    int by = blockIdx.y;
    if (by < blocks0) { A1 = A1g; A2 = A2g; Wr = Wrg; Wn = Wng; bias = bgg; out = outg; Nrows = N0; m0 = by * 128; }
    else              { A1 = A1s; A2 = A2s; Wr = Wrs; Wn = Wns; bias = bss; out = outs; Nrows = N1; m0 = (by - blocks0) * 128; }
    int n0 = blockIdx.x * 64;
    int tid = threadIdx.x, warp = tid >> 5, lane = tid & 31;
    int wm = warp >> 2, wn = warp & 3, lr = lane >> 2, lc = lane & 3;

    // resident B straight from weights: coalesced k-major float4 reads
    int kq = 1 << kq2;
    for (int i = tid; i < 64 * kq; i += 256) {
        int n = i >> kq2, k = (i & (kq - 1)) << 2;
        int ng = n0 + n;
        const float* src;
        if (mode == 0) src = (k < c) ? (Wr + (size_t)ng * c + k) : (Wn + (size_t)ng * c + (k - c));
        else           src = (ng < 192) ? (Wr + (size_t)ng * 256 + k) : (Wn + (size_t)(ng - 192) * 256 + k);
        float4 v = *(const float4*)src;
        Bp[n * bs + k + 0] = f2tf32(v.x);
        Bp[n * bs + k + 1] = f2tf32(v.y);
        Bp[n * bs + k + 2] = f2tf32(v.z);
        Bp[n * bs + k + 3] = f2tf32(v.w);
    }

    uint32_t b_base = (uint32_t)__cvta_generic_to_shared(Bp);
    uint32_t a_base0 = (uint32_t)__cvta_generic_to_shared(Ap);
    uint32_t a_base1 = a_base0 + 128 * 20 * 4;
    int arow = lane & 15, acolo = (lane >> 4) << 2;            // A ldmatrix.x4 addressing
    int browx = (lane & 7) + ((lane >> 4) << 3);               // B ldmatrix.x4: rows nb..+15
    int bcolx = ((lane >> 3) & 1) << 2;                        // cols {kq, kq+4}

    float acc[4][2][4] = {};
    int am = tid >> 2, akq = (tid & 3) << 2;
    int gm0 = m0 + am, gm1 = m0 + am + 64;
    float4 st0, st1;
    st0 = (gm0 < Nrows) ? *(const float4*)(A1 + (size_t)gm0 * c + akq) : make_float4(0.f, 0.f, 0.f, 0.f);
    st1 = (gm1 < Nrows) ? *(const float4*)(A1 + (size_t)gm1 * c + akq) : make_float4(0.f, 0.f, 0.f, 0.f);

    int iters = K >> 4;
    for (int it = 0; it < iters; it++) {
        uint32_t* Ab = Ap + (it & 1) * (128 * 20);
        uint32_t a_base = (it & 1) ? a_base1 : a_base0;
        *(uint4*)&Ab[am * 20 + akq]        = make_uint4(f2tf32(st0.x), f2tf32(st0.y), f2tf32(st0.z), f2tf32(st0.w));
        *(uint4*)&Ab[(am + 64) * 20 + akq] = make_uint4(f2tf32(st1.x), f2tf32(st1.y), f2tf32(st1.z), f2tf32(st1.w));
        __syncthreads();
        if (it + 1 < iters) {
            int k0 = (it + 1) << 4;
            const float* A = (k0 < c) ? A1 : A2;
            int col0 = (k0 < c) ? k0 : (k0 - c);
            st0 = (gm0 < Nrows) ? *(const float4*)(A + (size_t)gm0 * c + col0 + akq) : make_float4(0.f, 0.f, 0.f, 0.f);
            st1 = (gm1 < Nrows) ? *(const float4*)(A + (size_t)gm1 * c + col0 + akq) : make_float4(0.f, 0.f, 0.f, 0.f);
        }
        int kbase = it << 4;
        #pragma unroll
        for (int ks = 0; ks < 2; ks++) {
            int kq_ = ks << 3;
            uint32_t af[4][4];
            #pragma unroll
            for (int mt = 0; mt < 4; mt++) {
                int mb = wm * 64 + mt * 16;
                uint32_t addr = a_base + (uint32_t)(((mb + arow) * 20 + kq_ + acolo) << 2);
                ldsm_x4(af[mt][0], af[mt][1], af[mt][2], af[mt][3], addr);
            }
            // single x4 covers both n-tiles: m0=(nt0,kq), m1=(nt0,kq+4), m2=(nt1,kq), m3=(nt1,kq+4)
            uint32_t bf[2][2];
            {
                int nb = wn * 16;
                uint32_t addr = b_base + (uint32_t)(((nb + browx) * bs + kbase + kq_ + bcolx) << 2);
                ldsm_x4(bf[0][0], bf[0][1], bf[1][0], bf[1][1], addr);
            }
            #pragma unroll
            for (int nt = 0; nt < 2; nt++) {
                #pragma unroll
                for (int mt = 0; mt < 4; mt++) {
                    asm volatile(
                        "mma.sync.aligned.m16n8k8.row.col.f32.tf32.tf32.f32 "
                        "{%0,%1,%2,%3}, {%4,%5,%6,%7}, {%8,%9}, {%0,%1,%2,%3};"
                        : "+f"(acc[mt][nt][0]), "+f"(acc[mt][nt][1]),
                          "+f"(acc[mt][nt][2]), "+f"(acc[mt][nt][3])
                        : "r"(af[mt][0]), "r"(af[mt][1]), "r"(af[mt][2]), "r"(af[mt][3]),
                          "r"(bf[nt][0]), "r"(bf[nt][1]));
                }
            }
        }
    }

    int mrow0 = m0 + wm * 64;
    #pragma unroll
    for (int mt = 0; mt < 4; mt++) {
        #pragma unroll
        for (int half = 0; half < 2; half++) {
            int m = mrow0 + mt * 16 + lr + half * 8;
            if (m >= Nrows) continue;
            #pragma unroll
            for (int nt = 0; nt < 2; nt++) {
                int n = n0 + wn * 16 + nt * 8 + 2 * lc;
                float b0v, b1v;
                if (mode == 0) { b0v = bias[n]; b1v = bias[n + 1]; }
                else { b0v = (n >= 192) ? bias[n - 192] : 0.f; b1v = (n + 1 >= 192) ? bias[n + 1 - 192] : 0.f; }
                float v0 = acc[mt][nt][half * 2 + 0] + b0v;
                float v1 = acc[mt][nt][half * 2 + 1] + b1v;
                if (mode == 0) {
                    v0 = (v0 > 0.f) ? v0 : expm1f(v0);
                    v1 = (v1 > 0.f) ? v1 : expm1f(v1);
                }
                *(float2*)(out + (size_t)m * o + n) = make_float2(v0, v1);
            }
        }
    }
}

// ---------------- pooling (both branches, count fused; batch sorted) ----------------
__global__ void pool_c(const float* __restrict__ x3a, const int* __restrict__ ba,
                       float* __restrict__ pa, float* __restrict__ ca, int N0, int blocks0,
                       const float* __restrict__ x3b, const int* __restrict__ bb,
                       float* __restrict__ pb, float* __restrict__ cb, int N1) {
    const float* x3; const int* batch; float* pool; float* cnt; int N, blk;
    if ((int)blockIdx.x < blocks0) { x3 = x3a; batch = ba; pool = pa; cnt = ca; N = N0; blk = blockIdx.x; }
    else { x3 = x3b; batch = bb; pool = pb; cnt = cb; N = N1; blk = blockIdx.x - blocks0; }
    int t = threadIdx.x;   // 0..191
    int r0 = blk * 256;
    int rend = r0 + 256; if (rend > N) rend = N;
    if (r0 >= N) return;
    int cur = batch[r0];
    float acc = 0.f, cacc = 0.f;
    for (int i = r0; i < rend; i++) {
        int b = batch[i];
        if (b != cur) {
            atomicAdd(&pool[cur * 192 + t], acc);
            if (t == 0) atomicAdd(&cnt[cur], cacc);
            acc = 0.f; cacc = 0.f; cur = b;
        }
        float v = x3[(size_t)i * 384 + 192 + t];
        v = (v > 0.f) ? v : expm1f(v);
        acc += v; cacc += 1.f;
    }
    atomicAdd(&pool[cur * 192 + t], acc);
    if (t == 0) atomicAdd(&cnt[cur], cacc);
}

// ---------------- final MLP (single block): mean-div + 448->600->256->64 ----------------
__global__ void mlp_k(const float* __restrict__ point,
                      const float* __restrict__ l1W, const float* __restrict__ l1b,
                      const float* __restrict__ l2W, const float* __restrict__ l2b,
                      const float* __restrict__ l3W, const float* __restrict__ l3b,
                      const float* __restrict__ pool, const float* __restrict__ cnt,
                      float* __restrict__ out) {
    __shared__ float inT[448][8];
    __shared__ float h1[600][8];
    __shared__ float h2[256][8];
    int t = threadIdx.x;

    for (int idx = t; idx < 448 * 8; idx += blockDim.x) {
        int r = idx & 7, f = idx >> 3;
        float v;
        if (f < 192)       v = pool[r * 192 + f] / fmaxf(cnt[r], 1.f);
        else if (f < 384)  v = pool[1536 + r * 192 + (f - 192)] / fmaxf(cnt[8 + r], 1.f);
        else               v = point[r * 64 + (f - 384)];
        inT[f][r] = v;
    }
    __syncthreads();

    if (t < 600) {
        float acc[8];
        float b = l1b[t];
        #pragma unroll
        for (int r = 0; r < 8; r++) acc[r] = b;
        for (int f = 0; f < 448; f++) {
            float w = l1W[t * 448 + f];
            float4 p0 = *(const float4*)&inT[f][0];
            float4 p1 = *(const float4*)&inT[f][4];
            acc[0] += w * p0.x; acc[1] += w * p0.y; acc[2] += w * p0.z; acc[3] += w * p0.w;
            acc[4] += w * p1.x; acc[5] += w * p1.y; acc[6] += w * p1.z; acc[7] += w * p1.w;
        }
        #pragma unroll
        for (int r = 0; r < 8; r++) h1[t][r] = fmaxf(acc[r], 0.f);
    }
    __syncthreads();

    if (t < 256) {
        float acc[8];
        float b = l2b[t];
        #pragma unroll
        for (int r = 0; r < 8; r++) acc[r] = b;
        for (int f = 0; f < 600; f++) {
            float w = l2W[t * 600 + f];
            float4 p0 = *(const float4*)&h1[f][0];
            float4 p1 = *(const float4*)&h1[f][4];
            acc[0] += w * p0.x; acc[1] += w * p0.y; acc[2] += w * p0.z; acc[3] += w * p0.w;
            acc[4] += w * p1.x; acc[5] += w * p1.y; acc[6] += w * p1.z; acc[7] += w * p1.w;
        }
        #pragma unroll
        for (int r = 0; r < 8; r++) h2[t][r] = fmaxf(acc[r], 0.f);
    }
    __syncthreads();

    if (t < 64) {
        float acc[8];
        float b = l3b[t];
        #pragma unroll
        for (int r = 0; r < 8; r++) acc[r] = b;
        for (int f = 0; f < 256; f++) {
            float w = l3W[t * 256 + f];
            float4 p0 = *(const float4*)&h2[f][0];
            float4 p1 = *(const float4*)&h2[f][4];
            acc[0] += w * p0.x; acc[1] += w * p0.y; acc[2] += w * p0.z; acc[3] += w * p0.w;
            acc[4] += w * p1.x; acc[5] += w * p1.y; acc[6] += w * p1.z; acc[7] += w * p1.w;
        }
        #pragma unroll
        for (int r = 0; r < 8; r++) out[r * 64 + t] = acc[r];
    }
}

extern "C" void kernel_launch(void* const* d_in, const int* in_sizes, int n_in,
                              void* d_out, int out_size) {
    float* scratch = nullptr;
    cudaGetSymbolAddress((void**)&scratch, d_scratch);
    cudaFuncSetAttribute(gemm_c, cudaFuncAttributeMaxDynamicSharedMemorySize, 90112);

    // Resolve input ordering (dict order vs reference-signature order)
    int GX, SX, PT, GEI, GB, SEI, SB, GW, SW, LW;
    if (n_in >= 4 && in_sizes[3] == 2 * EG) {
        GX = 0; SX = 1; PT = 2; GEI = 3; GB = 4; SEI = 5; SB = 6;
        GW = 7; SW = 16; LW = 25;
    } else {
        GX = 0; SX = 1; PT = 2; GW = 3; SW = 12; LW = 21;
        GEI = 27; GB = 28; SEI = 29; SB = 30;
    }

    const float* x0g = (const float*)d_in[GX];
    const float* x0s = (const float*)d_in[SX];
    const int* eig = (const int*)d_in[GEI];
    const int* eis = (const int*)d_in[SEI];
    const int* bag = (const int*)d_in[GB];
    const int* bas = (const int*)d_in[SB];

    float* aggg = scratch + AGG_G;  float* aggs = scratch + AGG_S;
    float* x1g  = scratch + X1_G;   float* x1s  = scratch + X1_S;
    float* x2g  = scratch + X2_G;   float* x2s  = scratch + X2_S;
    float* x3g  = scratch + X3_G;   float* x3s  = scratch + X3_S;
    float* pool = scratch + POOL;
    float* cnt  = scratch + CNTO;
    int* degg = (int*)(scratch + DEG_G);   int* degs = (int*)(scratch + DEG_S);
    int* ptrg = (int*)(scratch + PTR_G);   int* ptrs = (int*)(scratch + PTR_S);
    int* filg = (int*)(scratch + FILL_G);  int* fils = (int*)(scratch + FILL_S);
    int* ssg  = (int*)(scratch + SS_G);    int* sss  = (int*)(scratch + SS_S);
    int* bsg  = (int*)(scratch + BS_G);    int* bss  = (int*)(scratch + BS_S);

    int b0 = (NG + 127) / 128, b1 = (NS + 127) / 128;
    int nbg = (NG + 255) / 256, nbs = (NS + 255) / 256;

    // zero pooled sums + counts, and degree arrays
    zero_k<<<(772 + 255) / 256, 256>>>((float4*)pool, 772);
    zero_k<<<(15001 + 255) / 256, 256>>>((float4*)(scratch + DEG_G), 15001);

    // ---- build CSR (once; shared by all three layers) ----
    {
        int tot = EG + ES;
        hist_c<<<(tot + 255) / 256, 256>>>(eig, EG, degg, eis, ES, degs);
        scan_blk<<<nbg + nbs, 256>>>(degg, ptrg, bsg, NG, nbg, degs, ptrs, bss, NS);
        scan_top<<<2, 256>>>(bsg, nbg, bss, nbs);
        scan_add<<<(NG + NS + 2 + 255) / 256, 256>>>(ptrg, filg, bsg, NG, nbg,
                                                     ptrs, fils, bss, NS, nbs);
        fill_c<<<(tot + 255) / 256, 256>>>(eig, EG, filg, ssg, eis, ES, fils, sss);
    }

    // ---- layer 1: c=64 -> o=128, K=128 (kq2=5)
    {
        int c = 64, o = 128, K = 128;
        int tot = (NG + NS) * 16;
        gather_c<<<(tot + 255) / 256, 256>>>(x0g, ptrg, ssg, aggg, NG,
                                             x0s, ptrs, sss, aggs, NS, c, 4);
        size_t smem = (size_t)(64 * (K + 4) + 2 * 128 * 20) * 4;
        gemm_c<<<dim3(o / 64, b0 + b1), 256, smem>>>(
            aggg, x0g, (const float*)d_in[GW + 0], (const float*)d_in[GW + 1],
            (const float*)d_in[GW + 2], x1g, NG,
            aggs, x0s, (const float*)d_in[SW + 0], (const float*)d_in[SW + 1],
            (const float*)d_in[SW + 2], x1s, NS,
            b0, c, K, 5, o, 0);
    }
    // ---- layer 2: c=128 -> o=256, K=256 (kq2=6)
    {
        int c = 128, o = 256, K = 256;
        int tot = (NG + NS) * 32;
        gather_c<<<(tot + 255) / 256, 256>>>(x1g, ptrg, ssg, aggg, NG,
                                             x1s, ptrs, sss, aggs, NS, c, 5);
        size_t smem = (size_t)(64 * (K + 4) + 2 * 128 * 20) * 4;
        gemm_c<<<dim3(o / 64, b0 + b1), 256, smem>>>(
            aggg, x1g, (const float*)d_in[GW + 3], (const float*)d_in[GW + 4],
            (const float*)d_in[GW + 5], x2g, NG,
            aggs, x1s, (const float*)d_in[SW + 3], (const float*)d_in[SW + 4],
            (const float*)d_in[SW + 5], x2s, NS,
            b0, c, K, 6, o, 0);
    }
    // ---- layer 3: GEMM first (linearity swap), then width-192 CSR gather, then pool
    {
        size_t smem = (size_t)(64 * (256 + 4) + 2 * 128 * 20) * 4;
        gemm_c<<<dim3(384 / 64, b0 + b1), 256, smem>>>(
            x2g, x2g, (const float*)d_in[GW + 6], (const float*)d_in[GW + 7],
            (const float*)d_in[GW + 8], x3g, NG,
            x2s, x2s, (const float*)d_in[SW + 6], (const float*)d_in[SW + 7],
            (const float*)d_in[SW + 8], x3s, NS,
            b0, 256, 256, 6, 384, 1);
        int tot = (NG + NS) * 48;
        gather3_c<<<(tot + 255) / 256, 256>>>(ptrg, ssg, x3g, NG, ptrs, sss, x3s, NS);
        int pb0 = (NG + 255) / 256, pb1 = (NS + 255) / 256;
        pool_c<<<pb0 + pb1, 192>>>(x3g, bag, pool, cnt, NG, pb0,
                                   x3s, bas, pool + 1536, cnt + 8, NS);
    }

    mlp_k<<<1, 640>>>((const float*)d_in[PT],
                      (const float*)d_in[LW + 0], (const float*)d_in[LW + 1],
                      (const float*)d_in[LW + 2], (const float*)d_in[LW + 3],
                      (const float*)d_in[LW + 4], (const float*)d_in[LW + 5],
                      pool, cnt, (float*)d_out);
}

// round 12
// speedup vs baseline: 5.6164x; 1.3394x over previous
#include <cuda_runtime.h>
#include <cuda_fp16.h>
#include <math.h>
#include <stdint.h>

#define NG 50000
#define NS 10000
#define EG 800000
#define ES 160000

// ---- scratch layout (float-indexed; half arrays alias 2 halfs per float) ----
static const size_t H0_G  = 0;         // NG*64 halfs = 1.6M floats
static const size_t H0_S  = 1600000;   // NS*64 halfs
static const size_t AGG_G = 2000000;   // NG*128 halfs max
static const size_t AGG_S = 5200000;
static const size_t X1_G  = 6000000;   // NG*128 halfs
static const size_t X1_S  = 9200000;
static const size_t X2_G  = 10000000;  // NG*256 halfs
static const size_t X2_S  = 16400000;
static const size_t X3_G  = 18000000;  // NG*384 halfs
static const size_t X3_S  = 27600000;
static const size_t POOL  = 30000000;  // 2*8*192 floats
static const size_t CNTO  = 30003072;  // 16 floats
static const size_t DEG_G = 30003104;  // ints
static const size_t DEG_S = 30053105;
static const size_t PTR_G = 30063106;
static const size_t PTR_S = 30113107;
static const size_t FILL_G= 30123108;
static const size_t FILL_S= 30173108;
static const size_t SS_G  = 30183108;
static const size_t SS_S  = 30983108;
static const size_t BS_G  = 31143108;
static const size_t BS_S  = 31143308;
__device__ float d_scratch[31143360];

__device__ __forceinline__ void ldsm_x4(uint32_t& r0, uint32_t& r1, uint32_t& r2, uint32_t& r3, uint32_t addr) {
    asm volatile("ldmatrix.sync.aligned.m8n8.x4.shared.b16 {%0,%1,%2,%3}, [%4];"
                 : "=r"(r0), "=r"(r1), "=r"(r2), "=r"(r3) : "r"(addr));
}

// ---------------- zero ----------------
__global__ void zero_k(float4* p, int n4) {
    int i = blockIdx.x * blockDim.x + threadIdx.x;
    if (i < n4) p[i] = make_float4(0.f, 0.f, 0.f, 0.f);
}

// ---------------- fp32 -> fp16 input conversion (both branches, one launch) ----------------
__global__ void cvt_in(const float* __restrict__ x0, __half* __restrict__ h0, int n2a,
                       const float* __restrict__ x1, __half* __restrict__ h1, int n2b) {
    int i = blockIdx.x * 256 + threadIdx.x;
    if (i < n2a) {
        float2 v = *(const float2*)(x0 + 2 * (size_t)i);
        *(__half2*)(h0 + 2 * (size_t)i) = __floats2half2_rn(v.x, v.y);
    } else {
        int j = i - n2a;
        if (j >= n2b) return;
        float2 v = *(const float2*)(x1 + 2 * (size_t)j);
        *(__half2*)(h1 + 2 * (size_t)j) = __floats2half2_rn(v.x, v.y);
    }
}

// ---------------- CSR build: histogram, 3-phase scan, fill ----------------
__global__ void hist_c(const int* __restrict__ ei0, int E0, int* __restrict__ deg0,
                       const int* __restrict__ ei1, int E1, int* __restrict__ deg1) {
    int i = blockIdx.x * 256 + threadIdx.x;
    if (i < E0) atomicAdd(&deg0[ei0[E0 + i]], 1);
    else {
        int j = i - E0;
        if (j < E1) atomicAdd(&deg1[ei1[E1 + j]], 1);
    }
}

__global__ void scan_blk(const int* __restrict__ dga, int* __restrict__ pta,
                         int* __restrict__ bsa, int Na, int nba,
                         const int* __restrict__ dgb, int* __restrict__ ptb,
                         int* __restrict__ bsb, int Nb) {
    const int* deg; int* ptr; int* bs; int N, b;
    if ((int)blockIdx.x < nba) { deg = dga; ptr = pta; bs = bsa; N = Na; b = blockIdx.x; }
    else                        { deg = dgb; ptr = ptb; bs = bsb; N = Nb; b = blockIdx.x - nba; }
    __shared__ int s[256];
    int t = threadIdx.x, i = b * 256 + t;
    int v = (i < N) ? deg[i] : 0;
    s[t] = v;
    __syncthreads();
    #pragma unroll
    for (int off = 1; off < 256; off <<= 1) {
        int u = (t >= off) ? s[t - off] : 0;
        __syncthreads();
        s[t] += u;
        __syncthreads();
    }
    if (i < N) ptr[i] = s[t] - v;
    if (t == 255) bs[b] = s[255];
}

__global__ void scan_top(int* __restrict__ bsa, int na, int* __restrict__ bsb, int nb) {
    int* bs; int n;
    if (blockIdx.x == 0) { bs = bsa; n = na; } else { bs = bsb; n = nb; }
    __shared__ int s[256];
    int t = threadIdx.x;
    int v = (t < n) ? bs[t] : 0;
    s[t] = v;
    __syncthreads();
    #pragma unroll
    for (int off = 1; off < 256; off <<= 1) {
        int u = (t >= off) ? s[t - off] : 0;
        __syncthreads();
        s[t] += u;
        __syncthreads();
    }
    if (t < n) bs[t] = s[t] - v;
    if (t == 255) bs[n] = s[255];
}

__global__ void scan_add(int* __restrict__ pta, int* __restrict__ fla,
                         const int* __restrict__ bsa, int Na, int nba,
                         int* __restrict__ ptb, int* __restrict__ flb,
                         const int* __restrict__ bsb, int Nb, int nbb) {
    int idx = blockIdx.x * 256 + threadIdx.x;
    int* ptr; int* fl; const int* bs; int N, i, nb;
    if (idx <= Na) { ptr = pta; fl = fla; bs = bsa; N = Na; i = idx; nb = nba; }
    else {
        i = idx - Na - 1;
        if (i > Nb) return;
        ptr = ptb; fl = flb; bs = bsb; N = Nb; nb = nbb;
    }
    if (i < N) {
        int p = ptr[i] + bs[i >> 8];
        ptr[i] = p;
        fl[i] = p;
    } else {
        ptr[N] = bs[nb];
    }
}

__global__ void fill_c(const int* __restrict__ ei0, int E0, int* __restrict__ fill0, int* __restrict__ ss0,
                       const int* __restrict__ ei1, int E1, int* __restrict__ fill1, int* __restrict__ ss1) {
    int i = blockIdx.x * 256 + threadIdx.x;
    if (i < E0) {
        int dst = ei0[E0 + i];
        int p = atomicAdd(&fill0[dst], 1);
        ss0[p] = ei0[i];
    } else {
        int j = i - E0;
        if (j >= E1) return;
        int dst = ei1[E1 + j];
        int p = atomicAdd(&fill1[dst], 1);
        ss1[p] = ei1[j];
    }
}

// ---------------- CSR gather (fp16 data, fp32 accumulate): thread owns 8 half-cols ----------------
__global__ void gather_h(const __half* __restrict__ x0, const int* __restrict__ ptr0,
                         const int* __restrict__ ss0, __half* __restrict__ agg0, int N0,
                         const __half* __restrict__ x1, const int* __restrict__ ptr1,
                         const int* __restrict__ ss1, __half* __restrict__ agg1, int N1,
                         int c, int shift) {
    int idx = blockIdx.x * 256 + threadIdx.x;
    const __half* x; const int* ptr; const int* ss; __half* agg; int i;
    int t0 = N0 << shift;
    if (idx < t0) { x = x0; ptr = ptr0; ss = ss0; agg = agg0; i = idx; }
    else {
        i = idx - t0;
        if (i >= (N1 << shift)) return;
        x = x1; ptr = ptr1; ss = ss1; agg = agg1;
    }
    int n = i >> shift;
    int q = (i & ((1 << shift) - 1)) << 3;    // half offset (8 halfs)
    int e0 = ptr[n], e1 = ptr[n + 1];
    float2 a[4];
    #pragma unroll
    for (int j = 0; j < 4; j++) a[j] = make_float2(0.f, 0.f);
    for (int e = e0; e < e1; e++) {
        int s = __ldg(ss + e);
        uint4 v = __ldg((const uint4*)(x + (size_t)s * c + q));
        const __half2* hv = (const __half2*)&v;
        #pragma unroll
        for (int j = 0; j < 4; j++) {
            float2 f = __half22float2(hv[j]);
            a[j].x += f.x; a[j].y += f.y;
        }
    }
    uint4 r;
    __half2* hr = (__half2*)&r;
    #pragma unroll
    for (int j = 0; j < 4; j++) hr[j] = __floats2half2_rn(a[j].x, a[j].y);
    *(uint4*)(agg + (size_t)n * c + q) = r;
}

// layer-3 gather: x3[n,192+q] += sum x3[src,q]  (rows 384 halfs; disjoint col ranges)
__global__ void gather3_h(const int* __restrict__ ptr0, const int* __restrict__ ss0,
                          __half* __restrict__ x30, int N0,
                          const int* __restrict__ ptr1, const int* __restrict__ ss1,
                          __half* __restrict__ x31, int N1) {
    int idx = blockIdx.x * 256 + threadIdx.x;
    const int* ptr; const int* ss; __half* x3; int i;
    int t0 = N0 * 24;
    if (idx < t0) { ptr = ptr0; ss = ss0; x3 = x30; i = idx; }
    else {
        i = idx - t0;
        if (i >= N1 * 24) return;
        ptr = ptr1; ss = ss1; x3 = x31;
    }
    int n = i / 24;
    int q = (i - n * 24) << 3;
    int e0 = ptr[n], e1 = ptr[n + 1];
    float2 a[4];
    {
        uint4 v = *(const uint4*)(x3 + (size_t)n * 384 + 192 + q);
        const __half2* hv = (const __half2*)&v;
        #pragma unroll
        for (int j = 0; j < 4; j++) a[j] = __half22float2(hv[j]);
    }
    for (int e = e0; e < e1; e++) {
        int s = __ldg(ss + e);
        uint4 v = __ldg((const uint4*)(x3 + (size_t)s * 384 + q));
        const __half2* hv = (const __half2*)&v;
        #pragma unroll
        for (int j = 0; j < 4; j++) {
            float2 f = __half22float2(hv[j]);
            a[j].x += f.x; a[j].y += f.y;
        }
    }
    uint4 r;
    __half2* hr = (__half2*)&r;
    #pragma unroll
    for (int j = 0; j < 4; j++) hr[j] = __floats2half2_rn(a[j].x, a[j].y);
    *(uint4*)(x3 + (size_t)n * 384 + 192 + q) = r;
}

// ---------------- fp16 GEMM (m16n8k16, fp32 accum): resident n-major B, reg-double-buffered A.
// mode 0: out = ELU([A1|A2(k>=c)] @ [Wr|Wn]^T + bias)
// mode 1: layer 3 — B row n = (n<192 ? W3r[n] : W3n[n-192]), bias = (n<192 ? 0 : B3[n-192])
__global__ void gemm_h(const __half* __restrict__ A1g, const __half* __restrict__ A2g,
                       const float* __restrict__ Wrg, const float* __restrict__ Wng,
                       const float* __restrict__ bgg, __half* __restrict__ outg, int N0,
                       const __half* __restrict__ A1s, const __half* __restrict__ A2s,
                       const float* __restrict__ Wrs, const float* __restrict__ Wns,
                       const float* __restrict__ bss, __half* __restrict__ outs, int N1,
                       int blocks0, int c, int K, int kq2, int o, int mode) {
    extern __shared__ __half smh[];
    int bsh = K + 8;
    __half* Bp = smh;                  // [64][K+8]
    __half* Ap = smh + 64 * bsh;       // [2][128][40]

    const __half *A1, *A2; const float *Wr, *Wn, *bias; __half* out; int Nrows, m0;
    int by = blockIdx.y;
    if (by < blocks0) { A1 = A1g; A2 = A2g; Wr = Wrg; Wn = Wng; bias = bgg; out = outg; Nrows = N0; m0 = by * 128; }
    else              { A1 = A1s; A2 = A2s; Wr = Wrs; Wn = Wns; bias = bss; out = outs; Nrows = N1; m0 = (by - blocks0) * 128; }
    int n0 = blockIdx.x * 64;
    int tid = threadIdx.x, warp = tid >> 5, lane = tid & 31;
    int wm = warp >> 2, wn = warp & 3, lr = lane >> 2, lc = lane & 3;

    // resident B straight from fp32 weights: coalesced k-major float4 reads -> 4 halfs
    int kq = 1 << kq2;   // float4 chunks per row (K/4)
    for (int i = tid; i < 64 * kq; i += 256) {
        int n = i >> kq2, k = (i & (kq - 1)) << 2;
        int ng = n0 + n;
        const float* src;
        if (mode == 0) src = (k < c) ? (Wr + (size_t)ng * c + k) : (Wn + (size_t)ng * c + (k - c));
        else           src = (ng < 192) ? (Wr + (size_t)ng * 256 + k) : (Wn + (size_t)(ng - 192) * 256 + k);
        float4 v = *(const float4*)src;
        __half2* dst = (__half2*)&Bp[n * bsh + k];
        dst[0] = __floats2half2_rn(v.x, v.y);
        dst[1] = __floats2half2_rn(v.z, v.w);
    }

    uint32_t b_base = (uint32_t)__cvta_generic_to_shared(Bp);
    uint32_t a_base0 = (uint32_t)__cvta_generic_to_shared(Ap);
    uint32_t a_base1 = a_base0 + 128 * 40 * 2;
    int arow = lane & 15, acolo = (lane >> 4) << 3;            // A ldmatrix.x4 addressing
    int browx = (lane & 7) + ((lane >> 4) << 3);               // B ldmatrix.x4 rows
    int bcolx = ((lane >> 3) & 1) << 3;                        // k cols {0, 8}

    float acc[4][2][4] = {};
    int am = tid >> 2, akc = (tid & 3) << 3;   // 8-half chunks: 4 per row
    int gm0 = m0 + am, gm1 = m0 + am + 64;
    uint4 st0, st1;
    const uint4 Z = make_uint4(0, 0, 0, 0);
    st0 = (gm0 < Nrows) ? *(const uint4*)(A1 + (size_t)gm0 * c + akc) : Z;
    st1 = (gm1 < Nrows) ? *(const uint4*)(A1 + (size_t)gm1 * c + akc) : Z;

    int iters = K >> 5;   // BK = 32 halfs
    for (int it = 0; it < iters; it++) {
        __half* Ab = Ap + (it & 1) * (128 * 40);
        uint32_t a_base = (it & 1) ? a_base1 : a_base0;
        *(uint4*)&Ab[am * 40 + akc]        = st0;
        *(uint4*)&Ab[(am + 64) * 40 + akc] = st1;
        __syncthreads();
        if (it + 1 < iters) {
            int k0 = (it + 1) << 5;
            const __half* A = (k0 < c) ? A1 : A2;
            int col0 = (k0 < c) ? k0 : (k0 - c);
            st0 = (gm0 < Nrows) ? *(const uint4*)(A + (size_t)gm0 * c + col0 + akc) : Z;
            st1 = (gm1 < Nrows) ? *(const uint4*)(A + (size_t)gm1 * c + col0 + akc) : Z;
        }
        int kbase = it << 5;
        #pragma unroll
        for (int ks = 0; ks < 2; ks++) {
            int kq_ = ks << 4;
            uint32_t af[4][4];
            #pragma unroll
            for (int mt = 0; mt < 4; mt++) {
                int mb = wm * 64 + mt * 16;
                uint32_t addr = a_base + (uint32_t)(((mb + arow) * 40 + kq_ + acolo) << 1);
                ldsm_x4(af[mt][0], af[mt][1], af[mt][2], af[mt][3], addr);
            }
            uint32_t bf[2][2];
            {
                int nb = wn * 16;
                uint32_t addr = b_base + (uint32_t)(((nb + browx) * bsh + kbase + kq_ + bcolx) << 1);
                ldsm_x4(bf[0][0], bf[0][1], bf[1][0], bf[1][1], addr);
            }
            #pragma unroll
            for (int nt = 0; nt < 2; nt++) {
                #pragma unroll
                for (int mt = 0; mt < 4; mt++) {
                    asm volatile(
                        "mma.sync.aligned.m16n8k16.row.col.f32.f16.f16.f32 "
                        "{%0,%1,%2,%3}, {%4,%5,%6,%7}, {%8,%9}, {%0,%1,%2,%3};"
                        : "+f"(acc[mt][nt][0]), "+f"(acc[mt][nt][1]),
                          "+f"(acc[mt][nt][2]), "+f"(acc[mt][nt][3])
                        : "r"(af[mt][0]), "r"(af[mt][1]), "r"(af[mt][2]), "r"(af[mt][3]),
                          "r"(bf[nt][0]), "r"(bf[nt][1]));
                }
            }
        }
    }

    int mrow0 = m0 + wm * 64;
    #pragma unroll
    for (int mt = 0; mt < 4; mt++) {
        #pragma unroll
        for (int half_ = 0; half_ < 2; half_++) {
            int m = mrow0 + mt * 16 + lr + half_ * 8;
            if (m >= Nrows) continue;
            #pragma unroll
            for (int nt = 0; nt < 2; nt++) {
                int n = n0 + wn * 16 + nt * 8 + 2 * lc;
                float b0v, b1v;
                if (mode == 0) { b0v = bias[n]; b1v = bias[n + 1]; }
                else { b0v = (n >= 192) ? bias[n - 192] : 0.f; b1v = (n + 1 >= 192) ? bias[n + 1 - 192] : 0.f; }
                float v0 = acc[mt][nt][half_ * 2 + 0] + b0v;
                float v1 = acc[mt][nt][half_ * 2 + 1] + b1v;
                if (mode == 0) {
                    v0 = (v0 > 0.f) ? v0 : expm1f(v0);
                    v1 = (v1 > 0.f) ? v1 : expm1f(v1);
                }
                *(__half2*)(out + (size_t)m * o + n) = __floats2half2_rn(v0, v1);
            }
        }
    }
}

// ---------------- pooling (both branches, count fused; batch sorted) ----------------
__global__ void pool_c(const __half* __restrict__ x3a, const int* __restrict__ ba,
                       float* __restrict__ pa, float* __restrict__ ca, int N0, int blocks0,
                       const __half* __restrict__ x3b, const int* __restrict__ bb,
                       float* __restrict__ pb, float* __restrict__ cb, int N1) {
    const __half* x3; const int* batch; float* pool; float* cnt; int N, blk;
    if ((int)blockIdx.x < blocks0) { x3 = x3a; batch = ba; pool = pa; cnt = ca; N = N0; blk = blockIdx.x; }
    else { x3 = x3b; batch = bb; pool = pb; cnt = cb; N = N1; blk = blockIdx.x - blocks0; }
    int t = threadIdx.x;   // 0..191
    int r0 = blk * 256;
    int rend = r0 + 256; if (rend > N) rend = N;
    if (r0 >= N) return;
    int cur = batch[r0];
    float acc = 0.f, cacc = 0.f;
    for (int i = r0; i < rend; i++) {
        int b = batch[i];
        if (b != cur) {
            atomicAdd(&pool[cur * 192 + t], acc);
            if (t == 0) atomicAdd(&cnt[cur], cacc);
            acc = 0.f; cacc = 0.f; cur = b;
        }
        float v = __half2float(x3[(size_t)i * 384 + 192 + t]);
        v = (v > 0.f) ? v : expm1f(v);
        acc += v; cacc += 1.f;
    }
    atomicAdd(&pool[cur * 192 + t], acc);
    if (t == 0) atomicAdd(&cnt[cur], cacc);
}

// ---------------- final MLP (single block): mean-div + 448->600->256->64 ----------------
__global__ void mlp_k(const float* __restrict__ point,
                      const float* __restrict__ l1W, const float* __restrict__ l1b,
                      const float* __restrict__ l2W, const float* __restrict__ l2b,
                      const float* __restrict__ l3W, const float* __restrict__ l3b,
                      const float* __restrict__ pool, const float* __restrict__ cnt,
                      float* __restrict__ out) {
    __shared__ float inT[448][8];
    __shared__ float h1[600][8];
    __shared__ float h2[256][8];
    int t = threadIdx.x;

    for (int idx = t; idx < 448 * 8; idx += blockDim.x) {
        int r = idx & 7, f = idx >> 3;
        float v;
        if (f < 192)       v = pool[r * 192 + f] / fmaxf(cnt[r], 1.f);
        else if (f < 384)  v = pool[1536 + r * 192 + (f - 192)] / fmaxf(cnt[8 + r], 1.f);
        else               v = point[r * 64 + (f - 384)];
        inT[f][r] = v;
    }
    __syncthreads();

    if (t < 600) {
        float acc[8];
        float b = l1b[t];
        #pragma unroll
        for (int r = 0; r < 8; r++) acc[r] = b;
        for (int f = 0; f < 448; f++) {
            float w = l1W[t * 448 + f];
            float4 p0 = *(const float4*)&inT[f][0];
            float4 p1 = *(const float4*)&inT[f][4];
            acc[0] += w * p0.x; acc[1] += w * p0.y; acc[2] += w * p0.z; acc[3] += w * p0.w;
            acc[4] += w * p1.x; acc[5] += w * p1.y; acc[6] += w * p1.z; acc[7] += w * p1.w;
        }
        #pragma unroll
        for (int r = 0; r < 8; r++) h1[t][r] = fmaxf(acc[r], 0.f);
    }
    __syncthreads();

    if (t < 256) {
        float acc[8];
        float b = l2b[t];
        #pragma unroll
        for (int r = 0; r < 8; r++) acc[r] = b;
        for (int f = 0; f < 600; f++) {
            float w = l2W[t * 600 + f];
            float4 p0 = *(const float4*)&h1[f][0];
            float4 p1 = *(const float4*)&h1[f][4];
            acc[0] += w * p0.x; acc[1] += w * p0.y; acc[2] += w * p0.z; acc[3] += w * p0.w;
            acc[4] += w * p1.x; acc[5] += w * p1.y; acc[6] += w * p1.z; acc[7] += w * p1.w;
        }
        #pragma unroll
        for (int r = 0; r < 8; r++) h2[t][r] = fmaxf(acc[r], 0.f);
    }
    __syncthreads();

    if (t < 64) {
        float acc[8];
        float b = l3b[t];
        #pragma unroll
        for (int r = 0; r < 8; r++) acc[r] = b;
        for (int f = 0; f < 256; f++) {
            float w = l3W[t * 256 + f];
            float4 p0 = *(const float4*)&h2[f][0];
            float4 p1 = *(const float4*)&h2[f][4];
            acc[0] += w * p0.x; acc[1] += w * p0.y; acc[2] += w * p0.z; acc[3] += w * p0.w;
            acc[4] += w * p1.x; acc[5] += w * p1.y; acc[6] += w * p1.z; acc[7] += w * p1.w;
        }
        #pragma unroll
        for (int r = 0; r < 8; r++) out[r * 64 + t] = acc[r];
    }
}

extern "C" void kernel_launch(void* const* d_in, const int* in_sizes, int n_in,
                              void* d_out, int out_size) {
    float* scratch = nullptr;
    cudaGetSymbolAddress((void**)&scratch, d_scratch);
    cudaFuncSetAttribute(gemm_h, cudaFuncAttributeMaxDynamicSharedMemorySize, 65536);

    // Resolve input ordering (dict order vs reference-signature order)
    int GX, SX, PT, GEI, GB, SEI, SB, GW, SW, LW;
    if (n_in >= 4 && in_sizes[3] == 2 * EG) {
        GX = 0; SX = 1; PT = 2; GEI = 3; GB = 4; SEI = 5; SB = 6;
        GW = 7; SW = 16; LW = 25;
    } else {
        GX = 0; SX = 1; PT = 2; GW = 3; SW = 12; LW = 21;
        GEI = 27; GB = 28; SEI = 29; SB = 30;
    }

    const float* x0g = (const float*)d_in[GX];
    const float* x0s = (const float*)d_in[SX];
    const int* eig = (const int*)d_in[GEI];
    const int* eis = (const int*)d_in[SEI];
    const int* bag = (const int*)d_in[GB];
    const int* bas = (const int*)d_in[SB];

    __half* h0g  = (__half*)(scratch + H0_G);   __half* h0s  = (__half*)(scratch + H0_S);
    __half* aggg = (__half*)(scratch + AGG_G);  __half* aggs = (__half*)(scratch + AGG_S);
    __half* x1g  = (__half*)(scratch + X1_G);   __half* x1s  = (__half*)(scratch + X1_S);
    __half* x2g  = (__half*)(scratch + X2_G);   __half* x2s  = (__half*)(scratch + X2_S);
    __half* x3g  = (__half*)(scratch + X3_G);   __half* x3s  = (__half*)(scratch + X3_S);
    float* pool = scratch + POOL;
    float* cnt  = scratch + CNTO;
    int* degg = (int*)(scratch + DEG_G);   int* degs = (int*)(scratch + DEG_S);
    int* ptrg = (int*)(scratch + PTR_G);   int* ptrs = (int*)(scratch + PTR_S);
    int* filg = (int*)(scratch + FILL_G);  int* fils = (int*)(scratch + FILL_S);
    int* ssg  = (int*)(scratch + SS_G);    int* sss  = (int*)(scratch + SS_S);
    int* bsg  = (int*)(scratch + BS_G);    int* bss  = (int*)(scratch + BS_S);

    int b0 = (NG + 127) / 128, b1 = (NS + 127) / 128;
    int nbg = (NG + 255) / 256, nbs = (NS + 255) / 256;

    // zero pooled sums + counts, and degree arrays
    zero_k<<<(772 + 255) / 256, 256>>>((float4*)pool, 772);
    zero_k<<<(15001 + 255) / 256, 256>>>((float4*)(scratch + DEG_G), 15001);

    // ---- convert inputs to fp16 (independent of CSR build) ----
    {
        int n2a = NG * 32, n2b = NS * 32;   // half2 counts
        cvt_in<<<(n2a + n2b + 255) / 256, 256>>>(x0g, h0g, n2a, x0s, h0s, n2b);
    }

    // ---- build CSR (once; shared by all three layers) ----
    {
        int tot = EG + ES;
        hist_c<<<(tot + 255) / 256, 256>>>(eig, EG, degg, eis, ES, degs);
        scan_blk<<<nbg + nbs, 256>>>(degg, ptrg, bsg, NG, nbg, degs, ptrs, bss, NS);
        scan_top<<<2, 256>>>(bsg, nbg, bss, nbs);
        scan_add<<<(NG + NS + 2 + 255) / 256, 256>>>(ptrg, filg, bsg, NG, nbg,
                                                     ptrs, fils, bss, NS, nbs);
        fill_c<<<(tot + 255) / 256, 256>>>(eig, EG, filg, ssg, eis, ES, fils, sss);
    }

    // ---- layer 1: c=64 -> o=128, K=128 (kq2=5: 32 float4/row)
    {
        int c = 64, o = 128, K = 128;
        int tot = (NG + NS) * 8;   // c/8 groups per node
        gather_h<<<(tot + 255) / 256, 256>>>(h0g, ptrg, ssg, aggg, NG,
                                             h0s, ptrs, sss, aggs, NS, c, 3);
        size_t smem = (size_t)(64 * (K + 8) + 2 * 128 * 40) * 2;
        gemm_h<<<dim3(o / 64, b0 + b1), 256, smem>>>(
            aggg, h0g, (const float*)d_in[GW + 0], (const float*)d_in[GW + 1],
            (const float*)d_in[GW + 2], x1g, NG,
            aggs, h0s, (const float*)d_in[SW + 0], (const float*)d_in[SW + 1],
            (const float*)d_in[SW + 2], x1s, NS,
            b0, c, K, 5, o, 0);
    }
    // ---- layer 2: c=128 -> o=256, K=256 (kq2=6)
    {
        int c = 128, o = 256, K = 256;
        int tot = (NG + NS) * 16;
        gather_h<<<(tot + 255) / 256, 256>>>(x1g, ptrg, ssg, aggg, NG,
                                             x1s, ptrs, sss, aggs, NS, c, 4);
        size_t smem = (size_t)(64 * (K + 8) + 2 * 128 * 40) * 2;
        gemm_h<<<dim3(o / 64, b0 + b1), 256, smem>>>(
            aggg, x1g, (const float*)d_in[GW + 3], (const float*)d_in[GW + 4],
            (const float*)d_in[GW + 5], x2g, NG,
            aggs, x1s, (const float*)d_in[SW + 3], (const float*)d_in[SW + 4],
            (const float*)d_in[SW + 5], x2s, NS,
            b0, c, K, 6, o, 0);
    }
    // ---- layer 3: GEMM first (linearity swap), then width-192 CSR gather, then pool
    {
        size_t smem = (size_t)(64 * (256 + 8) + 2 * 128 * 40) * 2;
        gemm_h<<<dim3(384 / 64, b0 + b1), 256, smem>>>(
            x2g, x2g, (const float*)d_in[GW + 6], (const float*)d_in[GW + 7],
            (const float*)d_in[GW + 8], x3g, NG,
            x2s, x2s, (const float*)d_in[SW + 6], (const float*)d_in[SW + 7],
            (const float*)d_in[SW + 8], x3s, NS,
            b0, 256, 256, 6, 384, 1);
        int tot = (NG + NS) * 24;
        gather3_h<<<(tot + 255) / 256, 256>>>(ptrg, ssg, x3g, NG, ptrs, sss, x3s, NS);
        int pb0 = (NG + 255) / 256, pb1 = (NS + 255) / 256;
        pool_c<<<pb0 + pb1, 192>>>(x3g, bag, pool, cnt, NG, pb0,
                                   x3s, bas, pool + 1536, cnt + 8, NS);
    }

    mlp_k<<<1, 640>>>((const float*)d_in[PT],
                      (const float*)d_in[LW + 0], (const float*)d_in[LW + 1],
                      (const float*)d_in[LW + 2], (const float*)d_in[LW + 3],
                      (const float*)d_in[LW + 4], (const float*)d_in[LW + 5],
                      pool, cnt, (float*)d_out);
}